// round 7
// baseline (speedup 1.0000x reference)
#include <cuda_runtime.h>
#include <cstdint>

#define BB 32
#define TT_ 256
#define CHL 16
#define CE_ 64
#define HC_ 64
#define HW_ 256
#define EMB_ 300
#define EIN_ 428
#define XS_ 432
#define LL_ 32
#define CV_ 128
#define NROW (BB*TT_)

__device__ float g_x[NROW*XS_];
// xg layout: [dir][t][p(64)][b(32)][gr(16)]  (gr = q*4+jj)
__device__ float g_xg[2][TT_*64*32*16];
__device__ float g_ctab[2][CV_*256];          // char input-projection table
__device__ float g_hs[NROW*512];              // [row][dir*256+k]  (for proj)
__device__ float g_hsT[TT_*2*256*32];         // [t][dir][k][b]    (for word exchange)
__device__ float g_feats[NROW*LL_];
__device__ unsigned g_cnt[2];
__device__ volatile unsigned g_epoch[2];

__device__ __forceinline__ float sigf(float x) { return 1.0f/(1.0f+__expf(-x)); }
__device__ __forceinline__ float tanh_(float x) {
    x = fmaxf(x, -43.0f);
    float e = __expf(-2.0f*x);
    return (1.0f - e)/(1.0f + e);
}

// ---- ctab[dir][c][g] = char_emb[c] . Wih[g]  (128 distinct chars only!) ----
// block (c, dir); also resets word barrier state (graph-replay determinism)
__global__ void ctab_kernel(const float* __restrict__ char_emb,
                            const float* __restrict__ Wf,
                            const float* __restrict__ Wb)
{
    __shared__ float e[64];
    const int c = blockIdx.x, dir = blockIdx.y;
    const float* W = dir ? Wb : Wf;
    const int g = threadIdx.x;
    if (c == 0 && dir == 0 && g < 2) { g_cnt[g] = 0u; g_epoch[g] = 0u; }
    if (g < 64) e[g] = char_emb[c*64 + g];
    __syncthreads();
    float s = 0.f;
    #pragma unroll
    for (int k = 0; k < 64; ++k) s += e[k]*W[g*64 + k];   // sequential k: bit-exact per row
    g_ctab[dir][c*256 + g] = s;
}

// ---- char recurrence + x assembly: 8 seqs/block, dir = blockIdx.y ----
__global__ void char_rec_kernel(
    const float* __restrict__ Whh_f, const float* __restrict__ bih_f, const float* __restrict__ bhh_f,
    const float* __restrict__ Whh_b, const float* __restrict__ bih_b, const float* __restrict__ bhh_b,
    const int* __restrict__ cseq,
    const int* __restrict__ sentence, const float* __restrict__ emb)
{
    extern __shared__ float sm[];
    const int P = 257;
    float* WhhT = sm;                 // [64][257]
    float* bsum = WhhT + 64*P;        // [256]
    float* hsm  = bsum + 256;         // [8][64]
    float* csm  = hsm + 512;          // [8][64]
    float* gts  = csm + 512;          // [8][256]
    __shared__ int cid[128];          // 8 seqs x 16 chars

    const int dir = blockIdx.y;
    const float* Whh = dir ? Whh_b : Whh_f;
    const float* bih = dir ? bih_b : bih_f;
    const float* bhh = dir ? bhh_b : bhh_f;
    const float* tab = g_ctab[dir];
    const int tid = threadIdx.x;
    const int seq0 = blockIdx.x*8;

    for (int u = tid; u < 256*64; u += 256) {
        int g = u >> 6, k = u & 63;
        WhhT[k*P + g] = Whh[u];
    }
    bsum[tid] = bih[tid] + bhh[tid];
    if (tid < 128) cid[tid] = cseq[seq0*CHL + tid];
    for (int u = tid; u < 512; u += 256) { hsm[u] = 0.f; csm[u] = 0.f; }
    __syncthreads();

    const int g = tid;
    for (int step = 0; step < 16; ++step) {
        int tcur = dir ? (15 - step) : step;
        float acc[8];
        #pragma unroll
        for (int s = 0; s < 8; ++s)
            acc[s] = bsum[g] + tab[cid[s*16 + tcur]*256 + g];
        #pragma unroll 4
        for (int k4 = 0; k4 < 16; ++k4) {
            float w[4];
            #pragma unroll
            for (int j = 0; j < 4; ++j) w[j] = WhhT[(k4*4+j)*P + g];
            #pragma unroll
            for (int s = 0; s < 8; ++s) {
                float4 h = ((float4*)hsm)[s*16 + k4];
                acc[s] += w[0]*h.x + w[1]*h.y + w[2]*h.z + w[3]*h.w;
            }
        }
        #pragma unroll
        for (int s = 0; s < 8; ++s) gts[s*256 + g] = acc[s];
        __syncthreads();
        #pragma unroll
        for (int r = 0; r < 2; ++r) {
            int u = tid + r*256;
            int s = u >> 6, j = u & 63;
            float i_ = sigf(gts[s*256 + j]);
            float f_ = sigf(gts[s*256 + 64 + j]);
            float gg = tanh_(gts[s*256 + 128 + j]);
            float o_ = sigf(gts[s*256 + 192 + j]);
            float c = f_*csm[u] + i_*gg;
            csm[u] = c;
            hsm[u] = o_*tanh_(c);
        }
        __syncthreads();
    }

    // x = [we(300), hb(64), hf(64), pad(4)]
    const int off = 300 + (dir ? 0 : 64);
    #pragma unroll
    for (int r = 0; r < 2; ++r) {
        int u = tid + r*256;
        int s = u >> 6, j = u & 63;
        g_x[(seq0 + s)*XS_ + off + j] = hsm[u];
    }
    if (dir == 1) {
        for (int u = tid; u < 600; u += 256) {       // 8 rows x 75 float4
            int s = u / 75, f4 = u % 75;
            int row = seq0 + s;
            int w = sentence[row];
            ((float4*)&g_x[row*XS_])[f4] = ((const float4*)&emb[w*EMB_])[f4];
        }
        if (tid < 8)
            *(float4*)&g_x[(seq0 + tid)*XS_ + 428] = make_float4(0.f,0.f,0.f,0.f);
    }
}

// ---- xg[dir] = x @ Wih^T (128x64 tile), float4 scatter into [t][p][b][gr] ----
__global__ void wih_gemm_kernel(const float* __restrict__ Wf,
                                const float* __restrict__ Wb)
{
    __shared__ float As[16*132];
    __shared__ float Bs[16*68];
    const int dir = blockIdx.z;
    const float* W = dir ? Wb : Wf;
    float* Cout = g_xg[dir];
    const int m0 = blockIdx.x*128, n0 = blockIdx.y*64;
    const int tid = threadIdx.x;
    const int tm = tid >> 4, tn = tid & 15;
    const int ar = tid >> 1, ac = tid & 1;
    const int br = tid >> 2, bc = tid & 3;

    float acc[8][4];
    #pragma unroll
    for (int i = 0; i < 8; ++i)
        #pragma unroll
        for (int j = 0; j < 4; ++j) acc[i][j] = 0.f;

    for (int k0 = 0; k0 < XS_; k0 += 16) {
        const float4* arow = (const float4*)&g_x[(m0+ar)*XS_ + k0];
        float4 a0 = arow[ac*2];
        float4 a1 = arow[ac*2+1];
        int kk = k0 + bc*4;
        float4 bv = make_float4(0.f,0.f,0.f,0.f);
        if (kk + 4 <= EIN_) bv = *(const float4*)&W[(n0+br)*EIN_ + kk];
        As[(ac*8+0)*132+ar]=a0.x; As[(ac*8+1)*132+ar]=a0.y;
        As[(ac*8+2)*132+ar]=a0.z; As[(ac*8+3)*132+ar]=a0.w;
        As[(ac*8+4)*132+ar]=a1.x; As[(ac*8+5)*132+ar]=a1.y;
        As[(ac*8+6)*132+ar]=a1.z; As[(ac*8+7)*132+ar]=a1.w;
        Bs[(bc*4+0)*68+br]=bv.x; Bs[(bc*4+1)*68+br]=bv.y;
        Bs[(bc*4+2)*68+br]=bv.z; Bs[(bc*4+3)*68+br]=bv.w;
        __syncthreads();
        #pragma unroll
        for (int k = 0; k < 16; ++k) {
            float4 aA = ((float4*)&As[k*132])[tm*2];
            float4 aB = ((float4*)&As[k*132])[tm*2+1];
            float4 b4 = ((float4*)&Bs[k*68])[tn];
            float av[8] = {aA.x,aA.y,aA.z,aA.w,aB.x,aB.y,aB.z,aB.w};
            #pragma unroll
            for (int i = 0; i < 8; ++i) {
                acc[i][0] += av[i]*b4.x; acc[i][1] += av[i]*b4.y;
                acc[i][2] += av[i]*b4.z; acc[i][3] += av[i]*b4.w;
            }
        }
        __syncthreads();
    }
    const int n = n0 + tn*4;
    const int q = n >> 8, p = (n >> 2) & 63;
    #pragma unroll
    for (int i = 0; i < 8; ++i) {
        int m = m0 + tm*8 + i;
        int b = m >> 8, t = m & 255;
        *(float4*)&Cout[((t*64 + p)*32 + b)*16 + q*4] =
            make_float4(acc[i][0], acc[i][1], acc[i][2], acc[i][3]);
    }
}

// ---- word BiLSTM v2: outer-product split-k, LDG h-exchange, 128 CTAs ----
// thread: kwarp = tid>>5 (k-slice of 32), q = (tid>>3)&3 (gate type), bg = tid&7 (4 batches)
__global__ void word_lstm_kernel(
    const float* __restrict__ Whh_f, const float* __restrict__ Whh_b,
    const float* __restrict__ bih_f, const float* __restrict__ bhh_f,
    const float* __restrict__ bih_b, const float* __restrict__ bhh_b)
{
    extern __shared__ float sm[];
    float* W4s    = sm;               // [k(256)][16]  (q*4+j fast)
    float* red    = W4s + 4096;       // [8][516]
    float* gates  = red + 8*516;      // [b(32)][17] padded
    float* c_s    = gates + 32*17;    // [32][4]
    float* bias_s = c_s + 128;        // [16]

    const int tid = threadIdx.x;
    const int dir = blockIdx.x >> 6;
    const int p   = blockIdx.x & 63;
    const float* Whh = dir ? Whh_b : Whh_f;
    const float* bi  = dir ? bih_b : bih_f;
    const float* bh  = dir ? bhh_b : bhh_f;
    const float* xg  = g_xg[dir];

    // W4s[k*16 + q*4 + j] = Whh[(q*256 + p*4 + j)*256 + k]   (coalesced reads)
    for (int u = tid; u < 4096; u += 256) {
        int r = u >> 8, k = u & 255;          // r = q*4+j
        int q = r >> 2, j = r & 3;
        W4s[k*16 + r] = Whh[(q*256 + p*4 + j)*256 + k];
    }
    if (tid < 16) {
        int q = tid >> 2, j = tid & 3;
        bias_s[tid] = bi[q*256 + p*4 + j] + bh[q*256 + p*4 + j];
    }
    if (tid < 128) c_s[tid] = 0.f;
    __syncthreads();

    const int kwarp = tid >> 5;
    const int q     = (tid >> 3) & 3;
    const int bg    = tid & 7;
    const int g0 = tid >> 5, b0 = tid & 31;   // reduce-phase indices (v=tid, tid+256)

    for (int it = 0; it < 256; ++it) {
        const int tcur = dir ? (255 - it) : it;

        // xg values needed at reduction (prefetch early, hides DRAM latency)
        float xv0 = xg[((tcur*64 + p)*32 + b0)*16 + g0];
        float xv1 = xg[((tcur*64 + p)*32 + b0)*16 + g0 + 8];

        float acc[4][4];
        #pragma unroll
        for (int j = 0; j < 4; ++j)
            #pragma unroll
            for (int bb = 0; bb < 4; ++bb) acc[j][bb] = 0.f;

        if (it > 0) {
            const int tprev = dir ? (tcur + 1) : (tcur - 1);
            const float4* hrow = (const float4*)&g_hsT[((tprev*2 + dir)*256)*32];
            #pragma unroll 4
            for (int i = 0; i < 32; ++i) {
                int k = kwarp*32 + i;
                float4 w4 = *(const float4*)&W4s[k*16 + q*4];
                float4 h4 = __ldcg(&hrow[k*8 + bg]);
                acc[0][0] += w4.x*h4.x; acc[0][1] += w4.x*h4.y; acc[0][2] += w4.x*h4.z; acc[0][3] += w4.x*h4.w;
                acc[1][0] += w4.y*h4.x; acc[1][1] += w4.y*h4.y; acc[1][2] += w4.y*h4.z; acc[1][3] += w4.y*h4.w;
                acc[2][0] += w4.z*h4.x; acc[2][1] += w4.z*h4.y; acc[2][2] += w4.z*h4.z; acc[2][3] += w4.z*h4.w;
                acc[3][0] += w4.w*h4.x; acc[3][1] += w4.w*h4.y; acc[3][2] += w4.w*h4.z; acc[3][3] += w4.w*h4.w;
            }
        }
        // partials: red[kwarp][ (q*4+j)*32 + bg*4 .. +3 ]
        #pragma unroll
        for (int j = 0; j < 4; ++j)
            *(float4*)&red[kwarp*516 + (q*4 + j)*32 + bg*4] =
                make_float4(acc[j][0], acc[j][1], acc[j][2], acc[j][3]);
        __syncthreads();

        // reduce 8 k-slices + bias + xg -> gates[b][g]
        {
            float s0 = bias_s[g0] + xv0;
            float s1 = bias_s[g0 + 8] + xv1;
            #pragma unroll
            for (int kw = 0; kw < 8; ++kw) {
                s0 += red[kw*516 + g0*32 + b0];
                s1 += red[kw*516 + (g0 + 8)*32 + b0];
            }
            gates[b0*17 + g0]     = s0;
            gates[b0*17 + g0 + 8] = s1;
        }
        __syncthreads();

        if (tid < 128) {
            int b = tid >> 2, j2 = tid & 3;
            float i_ = sigf(gates[b*17 + j2]);           // q=0
            float f_ = sigf(gates[b*17 + 4 + j2]);       // q=1
            float gg = tanh_(gates[b*17 + 8 + j2]);      // q=2
            float o_ = sigf(gates[b*17 + 12 + j2]);      // q=3
            float c = f_*c_s[tid] + i_*gg;
            c_s[tid] = c;
            float h = o_*tanh_(c);
            __stcg(&g_hsT[((tcur*2 + dir)*256 + p*4 + j2)*32 + b], h);
            g_hs[(b*256 + tcur)*512 + dir*256 + p*4 + j2] = h;   // for proj
        }
        __syncthreads();
        if (tid == 0) {
            __threadfence();
            unsigned old = atomicAdd(&g_cnt[dir], 1u);
            if (old == 64u*(unsigned)(it+1) - 1u) {
                __threadfence();
                g_epoch[dir] = (unsigned)(it + 1);
            }
            while (g_epoch[dir] < (unsigned)(it + 1)) { }
            __threadfence();
        }
        __syncthreads();
    }
}

// ---- feats = hs @ projW^T + b ----
__global__ void proj_kernel(const float* __restrict__ projW,
                            const float* __restrict__ projb)
{
    extern __shared__ float sm[];
    float* pw = sm;               // [512][33]
    float* hr = pw + 512*33;      // [8][512]
    const int tid = threadIdx.x;
    for (int u = tid; u < 32*512; u += 256) {
        int l = u >> 9, k = u & 511;
        pw[k*33 + l] = projW[u];
    }
    int row0 = blockIdx.x*8;
    for (int u = tid; u < 1024; u += 256)
        ((float4*)hr)[u] = ((const float4*)&g_hs[row0*512])[u];
    __syncthreads();

    int r = tid >> 5, l = tid & 31;
    float acc = projb[l];
    #pragma unroll 4
    for (int k4 = 0; k4 < 128; ++k4) {
        float4 h4 = ((float4*)hr)[r*128 + k4];
        acc += h4.x*pw[(k4*4+0)*33 + l] + h4.y*pw[(k4*4+1)*33 + l]
             + h4.z*pw[(k4*4+2)*33 + l] + h4.w*pw[(k4*4+3)*33 + l];
    }
    g_feats[(row0 + r)*32 + l] = acc;
}

// ---- viterbi: one warp per batch element ----
__global__ void viterbi_kernel(const float* __restrict__ trans, float* __restrict__ out)
{
    __shared__ float fv[32];
    __shared__ float tr[32*33];
    __shared__ unsigned char bpv[256*32];
    const int l = threadIdx.x, b = blockIdx.x;
    for (int u = l; u < 1024; u += 32) tr[(u>>5)*33 + (u&31)] = trans[u];
    fv[l] = -10000.0f;
    __syncwarp();

    for (int t = 0; t < 256; ++t) {
        float m = -1e30f; int am = 0;
        #pragma unroll
        for (int pi = 0; pi < 32; ++pi) {
            float s = fv[pi] + tr[l*33 + pi];
            if (s > m) { m = s; am = pi; }
        }
        bpv[t*32 + l] = (unsigned char)am;
        float nf = m + g_feats[(b*256 + t)*32 + l];
        __syncwarp();
        fv[l] = nf;
        __syncwarp();
    }
    if (l == 0) {
        float bm = fv[0]; int bt = 0;
        for (int pi = 1; pi < 32; ++pi) if (fv[pi] > bm) { bm = fv[pi]; bt = pi; }
        out[b] = bm;
        int tag = bt;
        for (int t = 255; t >= 0; --t) {
            out[32 + b*256 + t] = (float)tag;
            tag = (int)bpv[t*32 + tag];
        }
    }
}

extern "C" void kernel_launch(void* const* d_in, const int* in_sizes, int n_in,
                              void* d_out, int out_size)
{
    const int* sent = (const int*)d_in[0];
    const int* cseq = (const int*)d_in[1];
    const float* const* F = (const float* const*)(d_in + 2);
    // F: 0 emb, 1 char_emb, 2..5 cWih_f,cWhh_f,cbih_f,cbhh_f, 6..9 backward,
    //    10..13 wWih_f,wWhh_f,wbih_f,wbhh_f, 14..17 backward, 18 proj_W, 19 proj_b, 20 trans
    float* out = (float*)d_out;

    cudaFuncSetAttribute(char_rec_kernel,  cudaFuncAttributeMaxDynamicSharedMemorySize, 100000);
    cudaFuncSetAttribute(word_lstm_kernel, cudaFuncAttributeMaxDynamicSharedMemorySize, 40000);
    cudaFuncSetAttribute(proj_kernel,      cudaFuncAttributeMaxDynamicSharedMemorySize, 90000);

    ctab_kernel<<<dim3(CV_, 2), 256>>>(F[1], F[2], F[6]);
    char_rec_kernel<<<dim3(NROW/8, 2), 256, 79104>>>(
        F[3], F[4], F[5], F[7], F[8], F[9], cseq, sent, F[0]);
    wih_gemm_kernel<<<dim3(NROW/128, 1024/64, 2), 256>>>(F[10], F[14]);
    // smem: 4096 + 4128 + 544 + 128 + 16 = 8912 floats = 35648 B
    word_lstm_kernel<<<128, 256, 35648>>>(F[11], F[15], F[12], F[13], F[16], F[17]);
    proj_kernel<<<NROW/8, 256, 83968>>>(F[18], F[19]);
    viterbi_kernel<<<BB, 32>>>(F[20], out);
}

// round 8
// speedup vs baseline: 1.6897x; 1.6897x over previous
#include <cuda_runtime.h>
#include <cstdint>

#define BB 32
#define TT_ 256
#define CHL 16
#define CE_ 64
#define HC_ 64
#define HW_ 256
#define EMB_ 300
#define EIN_ 428
#define XS_ 432
#define LL_ 32
#define CV_ 128
#define NROW (BB*TT_)

__device__ float g_x[NROW*XS_];
// xg layout: [dir][t][p(64)][b(32)][gr(16)]  (gr = q*4+jj)
__device__ float g_xg[2][TT_*64*32*16];
__device__ float g_ctab[2][CV_*256];          // char input-projection table
__device__ float g_hs[NROW*512];              // [row][dir*256+k]
__device__ float g_feats[NROW*LL_];
__device__ unsigned g_cnt[2];
__device__ volatile unsigned g_epoch[2];

__device__ __forceinline__ float sigf(float x) { return 1.0f/(1.0f+__expf(-x)); }
__device__ __forceinline__ float tanh_(float x) {
    x = fmaxf(x, -43.0f);
    float e = __expf(-2.0f*x);
    return (1.0f - e)/(1.0f + e);
}

// ---- ctab[dir][c][g] = char_emb[c] . Wih[g]  (only 128 distinct chars) ----
// block (c, dir); block (0,0) also resets word barrier state (replay determinism)
__global__ void ctab_kernel(const float* __restrict__ char_emb,
                            const float* __restrict__ Wf,
                            const float* __restrict__ Wb)
{
    __shared__ float e[64];
    const int c = blockIdx.x, dir = blockIdx.y;
    const float* W = dir ? Wb : Wf;
    const int g = threadIdx.x;
    if (c == 0 && dir == 0 && g < 2) { g_cnt[g] = 0u; g_epoch[g] = 0u; }
    if (g < 64) e[g] = char_emb[c*64 + g];
    __syncthreads();
    float s = 0.f;
    #pragma unroll
    for (int k = 0; k < 64; ++k) s += e[k]*W[g*64 + k];   // sequential k: bit-exact
    g_ctab[dir][c*256 + g] = s;
}

// ---- char recurrence + x assembly: 8 seqs/block, dir = blockIdx.y ----
__global__ void char_rec_kernel(
    const float* __restrict__ Whh_f, const float* __restrict__ bih_f, const float* __restrict__ bhh_f,
    const float* __restrict__ Whh_b, const float* __restrict__ bih_b, const float* __restrict__ bhh_b,
    const int* __restrict__ cseq,
    const int* __restrict__ sentence, const float* __restrict__ emb)
{
    extern __shared__ float sm[];
    const int P = 257;
    float* WhhT = sm;                 // [64][257]
    float* bsum = WhhT + 64*P;        // [256]
    float* hsm  = bsum + 256;         // [8][64]
    float* csm  = hsm + 512;          // [8][64]
    float* gts  = csm + 512;          // [8][256]
    __shared__ int cid[128];          // 8 seqs x 16 chars

    const int dir = blockIdx.y;
    const float* Whh = dir ? Whh_b : Whh_f;
    const float* bih = dir ? bih_b : bih_f;
    const float* bhh = dir ? bhh_b : bhh_f;
    const float* tab = g_ctab[dir];
    const int tid = threadIdx.x;
    const int seq0 = blockIdx.x*8;

    for (int u = tid; u < 256*64; u += 256) {
        int g = u >> 6, k = u & 63;
        WhhT[k*P + g] = Whh[u];
    }
    bsum[tid] = bih[tid] + bhh[tid];
    if (tid < 128) cid[tid] = cseq[seq0*CHL + tid];
    for (int u = tid; u < 512; u += 256) { hsm[u] = 0.f; csm[u] = 0.f; }
    __syncthreads();

    const int g = tid;
    for (int step = 0; step < 16; ++step) {
        int tcur = dir ? (15 - step) : step;
        float acc[8];
        #pragma unroll
        for (int s = 0; s < 8; ++s)
            acc[s] = bsum[g] + tab[cid[s*16 + tcur]*256 + g];
        #pragma unroll 4
        for (int k4 = 0; k4 < 16; ++k4) {
            float w[4];
            #pragma unroll
            for (int j = 0; j < 4; ++j) w[j] = WhhT[(k4*4+j)*P + g];
            #pragma unroll
            for (int s = 0; s < 8; ++s) {
                float4 h = ((float4*)hsm)[s*16 + k4];
                acc[s] += w[0]*h.x + w[1]*h.y + w[2]*h.z + w[3]*h.w;
            }
        }
        #pragma unroll
        for (int s = 0; s < 8; ++s) gts[s*256 + g] = acc[s];
        __syncthreads();
        #pragma unroll
        for (int r = 0; r < 2; ++r) {
            int u = tid + r*256;
            int s = u >> 6, j = u & 63;
            float i_ = sigf(gts[s*256 + j]);
            float f_ = sigf(gts[s*256 + 64 + j]);
            float gg = tanh_(gts[s*256 + 128 + j]);
            float o_ = sigf(gts[s*256 + 192 + j]);
            float c = f_*csm[u] + i_*gg;
            csm[u] = c;
            hsm[u] = o_*tanh_(c);
        }
        __syncthreads();
    }

    // x = [we(300), hb(64), hf(64), pad(4)]
    const int off = 300 + (dir ? 0 : 64);
    #pragma unroll
    for (int r = 0; r < 2; ++r) {
        int u = tid + r*256;
        int s = u >> 6, j = u & 63;
        g_x[(seq0 + s)*XS_ + off + j] = hsm[u];
    }
    if (dir == 1) {
        for (int u = tid; u < 600; u += 256) {       // 8 rows x 75 float4
            int s = u / 75, f4 = u % 75;
            int row = seq0 + s;
            int w = sentence[row];
            ((float4*)&g_x[row*XS_])[f4] = ((const float4*)&emb[w*EMB_])[f4];
        }
        if (tid < 8)
            *(float4*)&g_x[(seq0 + tid)*XS_ + 428] = make_float4(0.f,0.f,0.f,0.f);
    }
}

// ---- xg[dir] = x @ Wih^T (128x64 tile), float4 scatter into [t][p][b][gr] ----
__global__ void wih_gemm_kernel(const float* __restrict__ Wf,
                                const float* __restrict__ Wb)
{
    __shared__ float As[16*132];
    __shared__ float Bs[16*68];
    const int dir = blockIdx.z;
    const float* W = dir ? Wb : Wf;
    float* Cout = g_xg[dir];
    const int m0 = blockIdx.x*128, n0 = blockIdx.y*64;
    const int tid = threadIdx.x;
    const int tm = tid >> 4, tn = tid & 15;
    const int ar = tid >> 1, ac = tid & 1;
    const int br = tid >> 2, bc = tid & 3;

    float acc[8][4];
    #pragma unroll
    for (int i = 0; i < 8; ++i)
        #pragma unroll
        for (int j = 0; j < 4; ++j) acc[i][j] = 0.f;

    for (int k0 = 0; k0 < XS_; k0 += 16) {
        const float4* arow = (const float4*)&g_x[(m0+ar)*XS_ + k0];
        float4 a0 = arow[ac*2];
        float4 a1 = arow[ac*2+1];
        int kk = k0 + bc*4;
        float4 bv = make_float4(0.f,0.f,0.f,0.f);
        if (kk + 4 <= EIN_) bv = *(const float4*)&W[(n0+br)*EIN_ + kk];
        As[(ac*8+0)*132+ar]=a0.x; As[(ac*8+1)*132+ar]=a0.y;
        As[(ac*8+2)*132+ar]=a0.z; As[(ac*8+3)*132+ar]=a0.w;
        As[(ac*8+4)*132+ar]=a1.x; As[(ac*8+5)*132+ar]=a1.y;
        As[(ac*8+6)*132+ar]=a1.z; As[(ac*8+7)*132+ar]=a1.w;
        Bs[(bc*4+0)*68+br]=bv.x; Bs[(bc*4+1)*68+br]=bv.y;
        Bs[(bc*4+2)*68+br]=bv.z; Bs[(bc*4+3)*68+br]=bv.w;
        __syncthreads();
        #pragma unroll
        for (int k = 0; k < 16; ++k) {
            float4 aA = ((float4*)&As[k*132])[tm*2];
            float4 aB = ((float4*)&As[k*132])[tm*2+1];
            float4 b4 = ((float4*)&Bs[k*68])[tn];
            float av[8] = {aA.x,aA.y,aA.z,aA.w,aB.x,aB.y,aB.z,aB.w};
            #pragma unroll
            for (int i = 0; i < 8; ++i) {
                acc[i][0] += av[i]*b4.x; acc[i][1] += av[i]*b4.y;
                acc[i][2] += av[i]*b4.z; acc[i][3] += av[i]*b4.w;
            }
        }
        __syncthreads();
    }
    const int n = n0 + tn*4;
    const int q = n >> 8, p = (n >> 2) & 63;
    #pragma unroll
    for (int i = 0; i < 8; ++i) {
        int m = m0 + tm*8 + i;
        int b = m >> 8, t = m & 255;
        *(float4*)&Cout[((t*64 + p)*32 + b)*16 + q*4] =
            make_float4(acc[i][0], acc[i][1], acc[i][2], acc[i][3]);
    }
}

// ---- word BiLSTM (R6 proven version): smem h-exchange, tid0 atomic barrier ----
__global__ void word_lstm_kernel(
    const float* __restrict__ Whh_f, const float* __restrict__ Whh_b,
    const float* __restrict__ bih_f, const float* __restrict__ bhh_f,
    const float* __restrict__ bih_b, const float* __restrict__ bhh_b)
{
    extern __shared__ float sm[];
    float* W4s   = sm;            // [64 k4][16 gr] x float4
    float* h_s   = W4s + 4096;    // [32][256]
    float* gates = h_s + 8192;    // [32][16]
    float* c_s   = gates + 512;   // [32][4]
    float* bias  = c_s + 128;     // [16]

    const int tid = threadIdx.x;
    const int dir = blockIdx.x >> 6;
    const int p   = blockIdx.x & 63;
    const float* Whh = dir ? Whh_b : Whh_f;
    const float* bi  = dir ? bih_b : bih_f;
    const float* bh  = dir ? bhh_b : bhh_f;
    const float* xg  = g_xg[dir];

    for (int u = tid; u < 1024; u += 256) {
        int k4 = u >> 4, gr = u & 15;
        int grow = (gr >> 2)*256 + p*4 + (gr & 3);
        ((float4*)W4s)[k4*16 + gr] = *(const float4*)&Whh[grow*256 + k4*4];
    }
    if (tid < 16) {
        int grow = (tid >> 2)*256 + p*4 + (tid & 3);
        bias[tid] = bi[grow] + bh[grow];
    }
    if (tid < 128) c_s[tid] = 0.f;
    __syncthreads();

    const int gr = tid & 15, bp = tid >> 4;
    const int b1 = bp, b2 = bp + 16;

    int t0 = dir ? 255 : 0;
    float x1 = xg[((t0*64 + p)*32 + b1)*16 + gr];
    float x2 = xg[((t0*64 + p)*32 + b2)*16 + gr];

    for (int it = 0; it < 256; ++it) {
        int tcur = dir ? (255 - it) : it;
        if (it == 0) {
            for (int u = tid; u < 8192; u += 256) h_s[u] = 0.f;
        } else {
            int tprev = dir ? (tcur + 1) : (tcur - 1);
            for (int u = tid; u < 2048; u += 256) {
                int b = u >> 6, k4 = u & 63;
                ((float4*)h_s)[b*64 + k4] =
                    __ldcg((const float4*)&g_hs[(b*256 + tprev)*512 + dir*256 + k4*4]);
            }
        }
        __syncthreads();

        float a1 = bias[gr] + x1;
        float a2 = bias[gr] + x2;
        if (it < 255) {
            int tn_ = dir ? (tcur - 1) : (tcur + 1);
            x1 = xg[((tn_*64 + p)*32 + b1)*16 + gr];
            x2 = xg[((tn_*64 + p)*32 + b2)*16 + gr];
        }
        #pragma unroll 8
        for (int k4 = 0; k4 < 64; ++k4) {
            float4 w  = ((float4*)W4s)[k4*16 + gr];
            float4 hA = ((float4*)h_s)[b1*64 + k4];
            float4 hB = ((float4*)h_s)[b2*64 + k4];
            a1 += w.x*hA.x + w.y*hA.y + w.z*hA.z + w.w*hA.w;
            a2 += w.x*hB.x + w.y*hB.y + w.z*hB.z + w.w*hB.w;
        }
        gates[b1*16 + gr] = a1;
        gates[b2*16 + gr] = a2;
        __syncthreads();

        if (tid < 128) {
            int b = tid >> 2, j2 = tid & 3;
            float i_ = sigf(gates[b*16 + j2]);
            float f_ = sigf(gates[b*16 + 4 + j2]);
            float gg = tanh_(gates[b*16 + 8 + j2]);
            float o_ = sigf(gates[b*16 + 12 + j2]);
            float c = f_*c_s[tid] + i_*gg;
            c_s[tid] = c;
            __stcg(&g_hs[(b*256 + tcur)*512 + dir*256 + p*4 + j2], o_*tanh_(c));
        }
        __syncthreads();
        if (tid == 0) {
            __threadfence();
            unsigned old = atomicAdd(&g_cnt[dir], 1u);
            if (old == 64u*(unsigned)(it+1) - 1u) {
                __threadfence();
                g_epoch[dir] = (unsigned)(it + 1);
            }
            while (g_epoch[dir] < (unsigned)(it + 1)) { }
            __threadfence();
        }
        __syncthreads();
    }
}

// ---- feats = hs @ projW^T + b ----
__global__ void proj_kernel(const float* __restrict__ projW,
                            const float* __restrict__ projb)
{
    extern __shared__ float sm[];
    float* pw = sm;               // [512][33]
    float* hr = pw + 512*33;      // [8][512]
    const int tid = threadIdx.x;
    for (int u = tid; u < 32*512; u += 256) {
        int l = u >> 9, k = u & 511;
        pw[k*33 + l] = projW[u];
    }
    int row0 = blockIdx.x*8;
    for (int u = tid; u < 1024; u += 256)
        ((float4*)hr)[u] = ((const float4*)&g_hs[row0*512])[u];
    __syncthreads();

    int r = tid >> 5, l = tid & 31;
    float acc = projb[l];
    #pragma unroll 4
    for (int k4 = 0; k4 < 128; ++k4) {
        float4 h4 = ((float4*)hr)[r*128 + k4];
        acc += h4.x*pw[(k4*4+0)*33 + l] + h4.y*pw[(k4*4+1)*33 + l]
             + h4.z*pw[(k4*4+2)*33 + l] + h4.w*pw[(k4*4+3)*33 + l];
    }
    g_feats[(row0 + r)*32 + l] = acc;
}

// ---- viterbi: one warp per batch element ----
__global__ void viterbi_kernel(const float* __restrict__ trans, float* __restrict__ out)
{
    __shared__ float fv[32];
    __shared__ float tr[32*33];
    __shared__ unsigned char bpv[256*32];
    const int l = threadIdx.x, b = blockIdx.x;
    for (int u = l; u < 1024; u += 32) tr[(u>>5)*33 + (u&31)] = trans[u];
    fv[l] = -10000.0f;
    __syncwarp();

    for (int t = 0; t < 256; ++t) {
        float m = -1e30f; int am = 0;
        #pragma unroll
        for (int pi = 0; pi < 32; ++pi) {
            float s = fv[pi] + tr[l*33 + pi];
            if (s > m) { m = s; am = pi; }
        }
        bpv[t*32 + l] = (unsigned char)am;
        float nf = m + g_feats[(b*256 + t)*32 + l];
        __syncwarp();
        fv[l] = nf;
        __syncwarp();
    }
    if (l == 0) {
        float bm = fv[0]; int bt = 0;
        for (int pi = 1; pi < 32; ++pi) if (fv[pi] > bm) { bm = fv[pi]; bt = pi; }
        out[b] = bm;
        int tag = bt;
        for (int t = 255; t >= 0; --t) {
            out[32 + b*256 + t] = (float)tag;
            tag = (int)bpv[t*32 + tag];
        }
    }
}

extern "C" void kernel_launch(void* const* d_in, const int* in_sizes, int n_in,
                              void* d_out, int out_size)
{
    const int* sent = (const int*)d_in[0];
    const int* cseq = (const int*)d_in[1];
    const float* const* F = (const float* const*)(d_in + 2);
    // F: 0 emb, 1 char_emb, 2..5 cWih_f,cWhh_f,cbih_f,cbhh_f, 6..9 backward,
    //    10..13 wWih_f,wWhh_f,wbih_f,wbhh_f, 14..17 backward, 18 proj_W, 19 proj_b, 20 trans
    float* out = (float*)d_out;

    cudaFuncSetAttribute(char_rec_kernel,  cudaFuncAttributeMaxDynamicSharedMemorySize, 100000);
    cudaFuncSetAttribute(word_lstm_kernel, cudaFuncAttributeMaxDynamicSharedMemorySize, 53000);
    cudaFuncSetAttribute(proj_kernel,      cudaFuncAttributeMaxDynamicSharedMemorySize, 90000);

    ctab_kernel<<<dim3(CV_, 2), 256>>>(F[1], F[2], F[6]);
    char_rec_kernel<<<dim3(NROW/8, 2), 256, 79104>>>(
        F[3], F[4], F[5], F[7], F[8], F[9], cseq, sent, F[0]);
    wih_gemm_kernel<<<dim3(NROW/128, 1024/64, 2), 256>>>(F[10], F[14]);
    word_lstm_kernel<<<128, 256, 51776>>>(F[11], F[15], F[12], F[13], F[16], F[17]);
    proj_kernel<<<NROW/8, 256, 83968>>>(F[18], F[19]);
    viterbi_kernel<<<BB, 32>>>(F[20], out);
}

// round 10
// speedup vs baseline: 2.1277x; 1.2593x over previous
#include <cuda_runtime.h>
#include <cstdint>

#define BB 32
#define TT_ 256
#define CHL 16
#define CE_ 64
#define HC_ 64
#define HW_ 256
#define EMB_ 300
#define EIN_ 428
#define XS_ 432
#define LL_ 32
#define CV_ 128
#define NROW (BB*TT_)

__device__ float g_x[NROW*XS_];
// xg layout: [dir][t][p(64)][b(32)][gr(16)]  (gr = q*4+jj)
__device__ float g_xg[2][TT_*64*32*16];
__device__ float g_ctab[2][CV_*256];          // char input-projection table
__device__ float g_hs[NROW*512];              // [row][dir*256+k]  (for proj)
__device__ float g_hsG[2*8*4*256];            // [dir][group][b(4)][k(256)] exchange buf
__device__ float g_feats[NROW*LL_];
__device__ unsigned g_cnt2[16];               // [dir*8+group]
__device__ volatile unsigned g_ep2[16];

__device__ __forceinline__ float sigf(float x) { return 1.0f/(1.0f+__expf(-x)); }
__device__ __forceinline__ float tanh_(float x) {
    x = fmaxf(x, -43.0f);
    float e = __expf(-2.0f*x);
    return (1.0f - e)/(1.0f + e);
}

// ---- ctab[dir][c][g] = char_emb[c] . Wih[g]  (only 128 distinct chars) ----
// block (0,0) also resets word barrier state (replay determinism)
__global__ void ctab_kernel(const float* __restrict__ char_emb,
                            const float* __restrict__ Wf,
                            const float* __restrict__ Wb)
{
    __shared__ float e[64];
    const int c = blockIdx.x, dir = blockIdx.y;
    const float* W = dir ? Wb : Wf;
    const int g = threadIdx.x;
    if (c == 0 && dir == 0 && g < 16) { g_cnt2[g] = 0u; g_ep2[g] = 0u; }
    if (g < 64) e[g] = char_emb[c*64 + g];
    __syncthreads();
    float s = 0.f;
    #pragma unroll
    for (int k = 0; k < 64; ++k) s += e[k]*W[g*64 + k];
    g_ctab[dir][c*256 + g] = s;
}

// ---- char recurrence + x assembly: 8 seqs/block, dir = blockIdx.y ----
__global__ void char_rec_kernel(
    const float* __restrict__ Whh_f, const float* __restrict__ bih_f, const float* __restrict__ bhh_f,
    const float* __restrict__ Whh_b, const float* __restrict__ bih_b, const float* __restrict__ bhh_b,
    const int* __restrict__ cseq,
    const int* __restrict__ sentence, const float* __restrict__ emb)
{
    extern __shared__ float sm[];
    const int P = 257;
    float* WhhT = sm;                 // [64][257]
    float* bsum = WhhT + 64*P;        // [256]
    float* hsm  = bsum + 256;         // [8][64]
    float* csm  = hsm + 512;          // [8][64]
    float* gts  = csm + 512;          // [8][256]
    __shared__ int cid[128];

    const int dir = blockIdx.y;
    const float* Whh = dir ? Whh_b : Whh_f;
    const float* bih = dir ? bih_b : bih_f;
    const float* bhh = dir ? bhh_b : bhh_f;
    const float* tab = g_ctab[dir];
    const int tid = threadIdx.x;
    const int seq0 = blockIdx.x*8;

    for (int u = tid; u < 256*64; u += 256) {
        int g = u >> 6, k = u & 63;
        WhhT[k*P + g] = Whh[u];
    }
    bsum[tid] = bih[tid] + bhh[tid];
    if (tid < 128) cid[tid] = cseq[seq0*CHL + tid];
    for (int u = tid; u < 512; u += 256) { hsm[u] = 0.f; csm[u] = 0.f; }
    __syncthreads();

    const int g = tid;
    for (int step = 0; step < 16; ++step) {
        int tcur = dir ? (15 - step) : step;
        float acc[8];
        #pragma unroll
        for (int s = 0; s < 8; ++s)
            acc[s] = bsum[g] + tab[cid[s*16 + tcur]*256 + g];
        #pragma unroll 4
        for (int k4 = 0; k4 < 16; ++k4) {
            float w[4];
            #pragma unroll
            for (int j = 0; j < 4; ++j) w[j] = WhhT[(k4*4+j)*P + g];
            #pragma unroll
            for (int s = 0; s < 8; ++s) {
                float4 h = ((float4*)hsm)[s*16 + k4];
                acc[s] += w[0]*h.x + w[1]*h.y + w[2]*h.z + w[3]*h.w;
            }
        }
        #pragma unroll
        for (int s = 0; s < 8; ++s) gts[s*256 + g] = acc[s];
        __syncthreads();
        #pragma unroll
        for (int r = 0; r < 2; ++r) {
            int u = tid + r*256;
            int s = u >> 6, j = u & 63;
            float i_ = sigf(gts[s*256 + j]);
            float f_ = sigf(gts[s*256 + 64 + j]);
            float gg = tanh_(gts[s*256 + 128 + j]);
            float o_ = sigf(gts[s*256 + 192 + j]);
            float c = f_*csm[u] + i_*gg;
            csm[u] = c;
            hsm[u] = o_*tanh_(c);
        }
        __syncthreads();
    }

    const int off = 300 + (dir ? 0 : 64);
    #pragma unroll
    for (int r = 0; r < 2; ++r) {
        int u = tid + r*256;
        int s = u >> 6, j = u & 63;
        g_x[(seq0 + s)*XS_ + off + j] = hsm[u];
    }
    if (dir == 1) {
        for (int u = tid; u < 600; u += 256) {
            int s = u / 75, f4 = u % 75;
            int row = seq0 + s;
            int w = sentence[row];
            ((float4*)&g_x[row*XS_])[f4] = ((const float4*)&emb[w*EMB_])[f4];
        }
        if (tid < 8)
            *(float4*)&g_x[(seq0 + tid)*XS_ + 428] = make_float4(0.f,0.f,0.f,0.f);
    }
}

// ---- xg[dir] = x @ Wih^T (128x64 tile), float4 scatter into [t][p][b][gr] ----
__global__ void wih_gemm_kernel(const float* __restrict__ Wf,
                                const float* __restrict__ Wb)
{
    __shared__ float As[16*132];
    __shared__ float Bs[16*68];
    const int dir = blockIdx.z;
    const float* W = dir ? Wb : Wf;
    float* Cout = g_xg[dir];
    const int m0 = blockIdx.x*128, n0 = blockIdx.y*64;
    const int tid = threadIdx.x;
    const int tm = tid >> 4, tn = tid & 15;
    const int ar = tid >> 1, ac = tid & 1;
    const int br = tid >> 2, bc = tid & 3;

    float acc[8][4];
    #pragma unroll
    for (int i = 0; i < 8; ++i)
        #pragma unroll
        for (int j = 0; j < 4; ++j) acc[i][j] = 0.f;

    for (int k0 = 0; k0 < XS_; k0 += 16) {
        const float4* arow = (const float4*)&g_x[(m0+ar)*XS_ + k0];
        float4 a0 = arow[ac*2];
        float4 a1 = arow[ac*2+1];
        int kk = k0 + bc*4;
        float4 bv = make_float4(0.f,0.f,0.f,0.f);
        if (kk + 4 <= EIN_) bv = *(const float4*)&W[(n0+br)*EIN_ + kk];
        As[(ac*8+0)*132+ar]=a0.x; As[(ac*8+1)*132+ar]=a0.y;
        As[(ac*8+2)*132+ar]=a0.z; As[(ac*8+3)*132+ar]=a0.w;
        As[(ac*8+4)*132+ar]=a1.x; As[(ac*8+5)*132+ar]=a1.y;
        As[(ac*8+6)*132+ar]=a1.z; As[(ac*8+7)*132+ar]=a1.w;
        Bs[(bc*4+0)*68+br]=bv.x; Bs[(bc*4+1)*68+br]=bv.y;
        Bs[(bc*4+2)*68+br]=bv.z; Bs[(bc*4+3)*68+br]=bv.w;
        __syncthreads();
        #pragma unroll
        for (int k = 0; k < 16; ++k) {
            float4 aA = ((float4*)&As[k*132])[tm*2];
            float4 aB = ((float4*)&As[k*132])[tm*2+1];
            float4 b4 = ((float4*)&Bs[k*68])[tn];
            float av[8] = {aA.x,aA.y,aA.z,aA.w,aB.x,aB.y,aB.z,aB.w};
            #pragma unroll
            for (int i = 0; i < 8; ++i) {
                acc[i][0] += av[i]*b4.x; acc[i][1] += av[i]*b4.y;
                acc[i][2] += av[i]*b4.z; acc[i][3] += av[i]*b4.w;
            }
        }
        __syncthreads();
    }
    const int n = n0 + tn*4;
    const int q = n >> 8, p = (n >> 2) & 63;
    #pragma unroll
    for (int i = 0; i < 8; ++i) {
        int m = m0 + tm*8 + i;
        int b = m >> 8, t = m & 255;
        *(float4*)&Cout[((t*64 + p)*32 + b)*16 + q*4] =
            make_float4(acc[i][0], acc[i][1], acc[i][2], acc[i][3]);
    }
}

// ---- word BiLSTM v3: batch-split groups of 8 CTAs, W in registers ----
// blockIdx.x: dir = bx>>6, group = (bx>>3)&7 (4 batches), c = bx&7 (32 units)
// thread: r = tid&127 (gate-row: q=r>>5, j=r&31), khalf = tid>>7
__global__ void __launch_bounds__(256, 1) word_lstm_kernel(
    const float* __restrict__ Whh_f, const float* __restrict__ Whh_b,
    const float* __restrict__ bih_f, const float* __restrict__ bhh_f,
    const float* __restrict__ bih_b, const float* __restrict__ bhh_b)
{
    __shared__ float hsm[4*256];        // [b(4)][k(256)]
    __shared__ float red[2*4*128];      // [khalf][b][row]
    __shared__ float bias_s[128];       // [row]

    const int tid = threadIdx.x;
    const int dir = blockIdx.x >> 6;
    const int grp = (blockIdx.x >> 3) & 7;
    const int c   = blockIdx.x & 7;
    const int u0  = c*32;
    const int bar = dir*8 + grp;
    const float* Whh = dir ? Whh_b : Whh_f;
    const float* bi  = dir ? bih_b : bih_f;
    const float* bh  = dir ? bhh_b : bhh_f;
    const float* xg  = g_xg[dir];
    float* hG = &g_hsG[(bar*4)*256];

    const int r = tid & 127, khalf = tid >> 7;
    const int q = r >> 5, j = r & 31;
    const int grow = q*256 + u0 + j;

    // weights into registers: 128 floats (this row's k-half)
    float w[128];
    #pragma unroll
    for (int i = 0; i < 32; ++i)
        ((float4*)w)[i] = *(const float4*)&Whh[grow*256 + khalf*128 + i*4];
    if (khalf == 0) bias_s[r] = bi[grow] + bh[grow];

    // activation-thread state (tid<128): owns (b = tid>>5, unit aj = tid&31)
    const int aj = tid & 31;
    const int au = u0 + aj;
    const int abg = grp*4 + (tid >> 5);             // global batch (tid<128)
    const int ap = au >> 2, agr_base = au & 3;
    float c_reg = 0.f;
    __syncthreads();

    for (int it = 0; it < 256; ++it) {
        const int tcur = dir ? (255 - it) : it;

        // prefetch xg for activation threads BEFORE the barrier wait
        float xv0=0.f, xv1=0.f, xv2=0.f, xv3=0.f;
        if (tid < 128) {
            const float* xr = &xg[((tcur*64 + ap)*32 + abg)*16];
            xv0 = xr[agr_base];      xv1 = xr[4 + agr_base];
            xv2 = xr[8 + agr_base];  xv3 = xr[12 + agr_base];
        }

        if (it == 0) {
            ((float4*)hsm)[tid] = make_float4(0.f,0.f,0.f,0.f);
        } else {
            if (tid == 0) {
                while (g_ep2[bar] < (unsigned)it) { }
                __threadfence();
            }
            __syncthreads();
            // stage group h (4 batches x 256) into smem: 1 float4/thread
            ((float4*)hsm)[tid] = __ldcg(&((const float4*)hG)[tid]);
        }
        __syncthreads();

        // gates: 4 batch accumulators, k-half dot with register weights
        {
            const float4* h0 = (const float4*)&hsm[0*256 + khalf*128];
            const float4* h1 = (const float4*)&hsm[1*256 + khalf*128];
            const float4* h2 = (const float4*)&hsm[2*256 + khalf*128];
            const float4* h3 = (const float4*)&hsm[3*256 + khalf*128];
            float a0=0.f, a1=0.f, a2=0.f, a3=0.f;
            #pragma unroll
            for (int k4 = 0; k4 < 32; ++k4) {
                float w0 = w[k4*4], w1 = w[k4*4+1], w2 = w[k4*4+2], w3 = w[k4*4+3];
                float4 v0 = h0[k4], v1 = h1[k4], v2 = h2[k4], v3 = h3[k4];
                a0 += w0*v0.x + w1*v0.y + w2*v0.z + w3*v0.w;
                a1 += w0*v1.x + w1*v1.y + w2*v1.z + w3*v1.w;
                a2 += w0*v2.x + w1*v2.y + w2*v2.z + w3*v2.w;
                a3 += w0*v3.x + w1*v3.y + w2*v3.z + w3*v3.w;
            }
            red[khalf*512 + 0*128 + r] = a0;
            red[khalf*512 + 1*128 + r] = a1;
            red[khalf*512 + 2*128 + r] = a2;
            red[khalf*512 + 3*128 + r] = a3;
        }
        __syncthreads();

        if (tid < 128) {
            const int b = tid >> 5;
            float s0 = bias_s[0*32 + aj] + xv0 + red[b*128 + 0*32 + aj] + red[512 + b*128 + 0*32 + aj];
            float s1 = bias_s[1*32 + aj] + xv1 + red[b*128 + 1*32 + aj] + red[512 + b*128 + 1*32 + aj];
            float s2 = bias_s[2*32 + aj] + xv2 + red[b*128 + 2*32 + aj] + red[512 + b*128 + 2*32 + aj];
            float s3 = bias_s[3*32 + aj] + xv3 + red[b*128 + 3*32 + aj] + red[512 + b*128 + 3*32 + aj];
            float i_ = sigf(s0), f_ = sigf(s1), gg = tanh_(s2), o_ = sigf(s3);
            float cc = f_*c_reg + i_*gg;
            c_reg = cc;
            float h = o_*tanh_(cc);
            __stcg(&hG[b*256 + au], h);
            g_hs[(abg*256 + tcur)*512 + dir*256 + au] = h;   // for proj
        }
        __syncthreads();
        if (tid == 0) {
            __threadfence();
            unsigned old = atomicAdd(&g_cnt2[bar], 1u);
            if (old == 8u*(unsigned)(it+1) - 1u) {
                __threadfence();
                g_ep2[bar] = (unsigned)(it + 1);
            }
        }
        // note: wait happens at top of next iteration (overlaps xg prefetch)
    }
}

// ---- feats = hs @ projW^T + b ----
__global__ void proj_kernel(const float* __restrict__ projW,
                            const float* __restrict__ projb)
{
    extern __shared__ float sm[];
    float* pw = sm;               // [512][33]
    float* hr = pw + 512*33;      // [8][512]
    const int tid = threadIdx.x;
    for (int u = tid; u < 32*512; u += 256) {
        int l = u >> 9, k = u & 511;
        pw[k*33 + l] = projW[u];
    }
    int row0 = blockIdx.x*8;
    for (int u = tid; u < 1024; u += 256)
        ((float4*)hr)[u] = ((const float4*)&g_hs[row0*512])[u];
    __syncthreads();

    int r = tid >> 5, l = tid & 31;
    float acc = projb[l];
    #pragma unroll 4
    for (int k4 = 0; k4 < 128; ++k4) {
        float4 h4 = ((float4*)hr)[r*128 + k4];
        acc += h4.x*pw[(k4*4+0)*33 + l] + h4.y*pw[(k4*4+1)*33 + l]
             + h4.z*pw[(k4*4+2)*33 + l] + h4.w*pw[(k4*4+3)*33 + l];
    }
    g_feats[(row0 + r)*32 + l] = acc;
}

// ---- viterbi: one warp per batch element ----
__global__ void viterbi_kernel(const float* __restrict__ trans, float* __restrict__ out)
{
    __shared__ float fv[32];
    __shared__ float tr[32*33];
    __shared__ unsigned char bpv[256*32];
    const int l = threadIdx.x, b = blockIdx.x;
    for (int u = l; u < 1024; u += 32) tr[(u>>5)*33 + (u&31)] = trans[u];
    fv[l] = -10000.0f;
    __syncwarp();

    for (int t = 0; t < 256; ++t) {
        float m = -1e30f; int am = 0;
        #pragma unroll
        for (int pi = 0; pi < 32; ++pi) {
            float s = fv[pi] + tr[l*33 + pi];
            if (s > m) { m = s; am = pi; }
        }
        bpv[t*32 + l] = (unsigned char)am;
        float nf = m + g_feats[(b*256 + t)*32 + l];
        __syncwarp();
        fv[l] = nf;
        __syncwarp();
    }
    if (l == 0) {
        float bm = fv[0]; int bt = 0;
        for (int pi = 1; pi < 32; ++pi) if (fv[pi] > bm) { bm = fv[pi]; bt = pi; }
        out[b] = bm;
        int tag = bt;
        for (int t = 255; t >= 0; --t) {
            out[32 + b*256 + t] = (float)tag;
            tag = (int)bpv[t*32 + tag];
        }
    }
}

extern "C" void kernel_launch(void* const* d_in, const int* in_sizes, int n_in,
                              void* d_out, int out_size)
{
    const int* sent = (const int*)d_in[0];
    const int* cseq = (const int*)d_in[1];
    const float* const* F = (const float* const*)(d_in + 2);
    // F: 0 emb, 1 char_emb, 2..5 cWih_f,cWhh_f,cbih_f,cbhh_f, 6..9 backward,
    //    10..13 wWih_f,wWhh_f,wbih_f,wbhh_f, 14..17 backward, 18 proj_W, 19 proj_b, 20 trans
    float* out = (float*)d_out;

    cudaFuncSetAttribute(char_rec_kernel,  cudaFuncAttributeMaxDynamicSharedMemorySize, 100000);
    cudaFuncSetAttribute(proj_kernel,      cudaFuncAttributeMaxDynamicSharedMemorySize, 90000);

    ctab_kernel<<<dim3(CV_, 2), 256>>>(F[1], F[2], F[6]);
    char_rec_kernel<<<dim3(NROW/8, 2), 256, 79104>>>(
        F[3], F[4], F[5], F[7], F[8], F[9], cseq, sent, F[0]);
    wih_gemm_kernel<<<dim3(NROW/128, 1024/64, 2), 256>>>(F[10], F[14]);
    word_lstm_kernel<<<128, 256>>>(F[11], F[15], F[12], F[13], F[16], F[17]);
    proj_kernel<<<NROW/8, 256, 83968>>>(F[18], F[19]);
    viterbi_kernel<<<BB, 32>>>(F[20], out);
}

// round 11
// speedup vs baseline: 2.1512x; 1.0111x over previous
#include <cuda_runtime.h>
#include <cstdint>

#define BB 32
#define TT_ 256
#define CHL 16
#define CE_ 64
#define HC_ 64
#define HW_ 256
#define EMB_ 300
#define EIN_ 428
#define XS_ 432
#define LL_ 32
#define CV_ 128
#define NROW (BB*TT_)

__device__ float g_x[NROW*XS_];
// xg layout: [dir][t][p(64)][b(32)][gr(16)]  (gr = q*4+jj)
__device__ float g_xg[2][TT_*64*32*16];
__device__ float g_ctab[2][CV_*256];          // char input-projection table
__device__ float g_hs[NROW*512];              // [row][dir*256+k]  (for proj)
__device__ float g_feats[NROW*LL_];

__device__ __forceinline__ float sigf(float x) { return 1.0f/(1.0f+__expf(-x)); }
__device__ __forceinline__ float tanh_(float x) {
    x = fmaxf(x, -43.0f);
    float e = __expf(-2.0f*x);
    return (1.0f - e)/(1.0f + e);
}

__device__ __forceinline__ uint32_t smem_u32(const void* p) {
    uint32_t a;
    asm("{ .reg .u64 t; cvta.to.shared.u64 t, %1; cvt.u32.u64 %0, t; }"
        : "=r"(a) : "l"(p));
    return a;
}
__device__ __forceinline__ void st_cluster_f32(uint32_t laddr, int rank, float v) {
    uint32_t rem;
    asm volatile("mapa.shared::cluster.u32 %0, %1, %2;" : "=r"(rem) : "r"(laddr), "r"(rank));
    asm volatile("st.shared::cluster.f32 [%0], %1;" :: "r"(rem), "f"(v) : "memory");
}
#define CLUSTER_SYNC() do { \
    asm volatile("barrier.cluster.arrive.aligned;" ::: "memory"); \
    asm volatile("barrier.cluster.wait.aligned;" ::: "memory"); \
} while(0)

// ---- ctab[dir][c][g] = char_emb[c] . Wih[g]  (only 128 distinct chars) ----
__global__ void ctab_kernel(const float* __restrict__ char_emb,
                            const float* __restrict__ Wf,
                            const float* __restrict__ Wb)
{
    __shared__ float e[64];
    const int c = blockIdx.x, dir = blockIdx.y;
    const float* W = dir ? Wb : Wf;
    const int g = threadIdx.x;
    if (g < 64) e[g] = char_emb[c*64 + g];
    __syncthreads();
    float s = 0.f;
    #pragma unroll
    for (int k = 0; k < 64; ++k) s += e[k]*W[g*64 + k];
    g_ctab[dir][c*256 + g] = s;
}

// ---- char recurrence + x assembly: 8 seqs/block, dir = blockIdx.y ----
__global__ void char_rec_kernel(
    const float* __restrict__ Whh_f, const float* __restrict__ bih_f, const float* __restrict__ bhh_f,
    const float* __restrict__ Whh_b, const float* __restrict__ bih_b, const float* __restrict__ bhh_b,
    const int* __restrict__ cseq,
    const int* __restrict__ sentence, const float* __restrict__ emb)
{
    extern __shared__ float sm[];
    const int P = 257;
    float* WhhT = sm;                 // [64][257]
    float* bsum = WhhT + 64*P;        // [256]
    float* hsm  = bsum + 256;         // [8][64]
    float* csm  = hsm + 512;          // [8][64]
    float* gts  = csm + 512;          // [8][256]
    __shared__ int cid[128];

    const int dir = blockIdx.y;
    const float* Whh = dir ? Whh_b : Whh_f;
    const float* bih = dir ? bih_b : bih_f;
    const float* bhh = dir ? bhh_b : bhh_f;
    const float* tab = g_ctab[dir];
    const int tid = threadIdx.x;
    const int seq0 = blockIdx.x*8;

    for (int u = tid; u < 256*64; u += 256) {
        int g = u >> 6, k = u & 63;
        WhhT[k*P + g] = Whh[u];
    }
    bsum[tid] = bih[tid] + bhh[tid];
    if (tid < 128) cid[tid] = cseq[seq0*CHL + tid];
    for (int u = tid; u < 512; u += 256) { hsm[u] = 0.f; csm[u] = 0.f; }
    __syncthreads();

    const int g = tid;
    for (int step = 0; step < 16; ++step) {
        int tcur = dir ? (15 - step) : step;
        float acc[8];
        #pragma unroll
        for (int s = 0; s < 8; ++s)
            acc[s] = bsum[g] + tab[cid[s*16 + tcur]*256 + g];
        #pragma unroll 4
        for (int k4 = 0; k4 < 16; ++k4) {
            float w[4];
            #pragma unroll
            for (int j = 0; j < 4; ++j) w[j] = WhhT[(k4*4+j)*P + g];
            #pragma unroll
            for (int s = 0; s < 8; ++s) {
                float4 h = ((float4*)hsm)[s*16 + k4];
                acc[s] += w[0]*h.x + w[1]*h.y + w[2]*h.z + w[3]*h.w;
            }
        }
        #pragma unroll
        for (int s = 0; s < 8; ++s) gts[s*256 + g] = acc[s];
        __syncthreads();
        #pragma unroll
        for (int r = 0; r < 2; ++r) {
            int u = tid + r*256;
            int s = u >> 6, j = u & 63;
            float i_ = sigf(gts[s*256 + j]);
            float f_ = sigf(gts[s*256 + 64 + j]);
            float gg = tanh_(gts[s*256 + 128 + j]);
            float o_ = sigf(gts[s*256 + 192 + j]);
            float c = f_*csm[u] + i_*gg;
            csm[u] = c;
            hsm[u] = o_*tanh_(c);
        }
        __syncthreads();
    }

    const int off = 300 + (dir ? 0 : 64);
    #pragma unroll
    for (int r = 0; r < 2; ++r) {
        int u = tid + r*256;
        int s = u >> 6, j = u & 63;
        g_x[(seq0 + s)*XS_ + off + j] = hsm[u];
    }
    if (dir == 1) {
        for (int u = tid; u < 600; u += 256) {
            int s = u / 75, f4 = u % 75;
            int row = seq0 + s;
            int w = sentence[row];
            ((float4*)&g_x[row*XS_])[f4] = ((const float4*)&emb[w*EMB_])[f4];
        }
        if (tid < 8)
            *(float4*)&g_x[(seq0 + tid)*XS_ + 428] = make_float4(0.f,0.f,0.f,0.f);
    }
}

// ---- xg[dir] = x @ Wih^T (128x64 tile), float4 scatter into [t][p][b][gr] ----
__global__ void wih_gemm_kernel(const float* __restrict__ Wf,
                                const float* __restrict__ Wb)
{
    __shared__ float As[16*132];
    __shared__ float Bs[16*68];
    const int dir = blockIdx.z;
    const float* W = dir ? Wb : Wf;
    float* Cout = g_xg[dir];
    const int m0 = blockIdx.x*128, n0 = blockIdx.y*64;
    const int tid = threadIdx.x;
    const int tm = tid >> 4, tn = tid & 15;
    const int ar = tid >> 1, ac = tid & 1;
    const int br = tid >> 2, bc = tid & 3;

    float acc[8][4];
    #pragma unroll
    for (int i = 0; i < 8; ++i)
        #pragma unroll
        for (int j = 0; j < 4; ++j) acc[i][j] = 0.f;

    for (int k0 = 0; k0 < XS_; k0 += 16) {
        const float4* arow = (const float4*)&g_x[(m0+ar)*XS_ + k0];
        float4 a0 = arow[ac*2];
        float4 a1 = arow[ac*2+1];
        int kk = k0 + bc*4;
        float4 bv = make_float4(0.f,0.f,0.f,0.f);
        if (kk + 4 <= EIN_) bv = *(const float4*)&W[(n0+br)*EIN_ + kk];
        As[(ac*8+0)*132+ar]=a0.x; As[(ac*8+1)*132+ar]=a0.y;
        As[(ac*8+2)*132+ar]=a0.z; As[(ac*8+3)*132+ar]=a0.w;
        As[(ac*8+4)*132+ar]=a1.x; As[(ac*8+5)*132+ar]=a1.y;
        As[(ac*8+6)*132+ar]=a1.z; As[(ac*8+7)*132+ar]=a1.w;
        Bs[(bc*4+0)*68+br]=bv.x; Bs[(bc*4+1)*68+br]=bv.y;
        Bs[(bc*4+2)*68+br]=bv.z; Bs[(bc*4+3)*68+br]=bv.w;
        __syncthreads();
        #pragma unroll
        for (int k = 0; k < 16; ++k) {
            float4 aA = ((float4*)&As[k*132])[tm*2];
            float4 aB = ((float4*)&As[k*132])[tm*2+1];
            float4 b4 = ((float4*)&Bs[k*68])[tn];
            float av[8] = {aA.x,aA.y,aA.z,aA.w,aB.x,aB.y,aB.z,aB.w};
            #pragma unroll
            for (int i = 0; i < 8; ++i) {
                acc[i][0] += av[i]*b4.x; acc[i][1] += av[i]*b4.y;
                acc[i][2] += av[i]*b4.z; acc[i][3] += av[i]*b4.w;
            }
        }
        __syncthreads();
    }
    const int n = n0 + tn*4;
    const int q = n >> 8, p = (n >> 2) & 63;
    #pragma unroll
    for (int i = 0; i < 8; ++i) {
        int m = m0 + tm*8 + i;
        int b = m >> 8, t = m & 255;
        *(float4*)&Cout[((t*64 + p)*32 + b)*16 + q*4] =
            make_float4(acc[i][0], acc[i][1], acc[i][2], acc[i][3]);
    }
}

// ---- word BiLSTM v4: clusters of 8 CTAs, DSMEM h-exchange, W in registers ----
// blockIdx.x: dir = bx>>6, group = (bx>>3)&7 (4 batches), rank c = bx&7 (32 units)
__global__ void __launch_bounds__(256, 1) __cluster_dims__(8, 1, 1)
word_lstm_kernel(
    const float* __restrict__ Whh_f, const float* __restrict__ Whh_b,
    const float* __restrict__ bih_f, const float* __restrict__ bhh_f,
    const float* __restrict__ bih_b, const float* __restrict__ bhh_b)
{
    __shared__ float hsm[2][4*256];     // double-buffered [b(4)][k(256)]
    __shared__ float red[2*4*128];      // [khalf][b][row]
    __shared__ float bias_s[128];       // [row]

    const int tid = threadIdx.x;
    const int dir = blockIdx.x >> 6;
    const int grp = (blockIdx.x >> 3) & 7;
    const int c   = blockIdx.x & 7;     // == cluster rank
    const int u0  = c*32;
    const float* Whh = dir ? Whh_b : Whh_f;
    const float* bi  = dir ? bih_b : bih_f;
    const float* bh  = dir ? bhh_b : bhh_f;
    const float* xg  = g_xg[dir];
    const uint32_t hsm_a = smem_u32(hsm);

    const int r = tid & 127, khalf = tid >> 7;
    const int q = r >> 5, j = r & 31;
    const int grow = q*256 + u0 + j;

    // weights into registers: 128 floats (this row's k-half)
    float w[128];
    #pragma unroll
    for (int i = 0; i < 32; ++i)
        ((float4*)w)[i] = *(const float4*)&Whh[grow*256 + khalf*128 + i*4];
    if (khalf == 0) bias_s[r] = bi[grow] + bh[grow];

    // activation-thread state (tid<128): owns (b = tid>>5, unit aj = tid&31)
    const int aj = tid & 31;
    const int au = u0 + aj;
    const int abg = grp*4 + (tid >> 5);             // global batch (tid<128)
    const int ap = au >> 2, agr_base = au & 3;
    float c_reg = 0.f;

    ((float4*)hsm[0])[tid] = make_float4(0.f,0.f,0.f,0.f);   // step-0 h = 0
    __syncthreads();
    CLUSTER_SYNC();                                          // peers initialized

    for (int it = 0; it < 256; ++it) {
        const int tcur = dir ? (255 - it) : it;
        const int rb = it & 1, wb = rb ^ 1;

        // prefetch xg for activation threads (hidden under FMA loop)
        float xv0=0.f, xv1=0.f, xv2=0.f, xv3=0.f;
        if (tid < 128) {
            const float* xr = &xg[((tcur*64 + ap)*32 + abg)*16];
            xv0 = xr[agr_base];      xv1 = xr[4 + agr_base];
            xv2 = xr[8 + agr_base];  xv3 = xr[12 + agr_base];
        }

        // gates: 4 batch accumulators, k-half dot with register weights
        {
            const float4* h0 = (const float4*)&hsm[rb][0*256 + khalf*128];
            const float4* h1 = (const float4*)&hsm[rb][1*256 + khalf*128];
            const float4* h2 = (const float4*)&hsm[rb][2*256 + khalf*128];
            const float4* h3 = (const float4*)&hsm[rb][3*256 + khalf*128];
            float a0=0.f, a1=0.f, a2=0.f, a3=0.f;
            #pragma unroll
            for (int k4 = 0; k4 < 32; ++k4) {
                float w0 = w[k4*4], w1 = w[k4*4+1], w2 = w[k4*4+2], w3 = w[k4*4+3];
                float4 v0 = h0[k4], v1 = h1[k4], v2 = h2[k4], v3 = h3[k4];
                a0 += w0*v0.x + w1*v0.y + w2*v0.z + w3*v0.w;
                a1 += w0*v1.x + w1*v1.y + w2*v1.z + w3*v1.w;
                a2 += w0*v2.x + w1*v2.y + w2*v2.z + w3*v2.w;
                a3 += w0*v3.x + w1*v3.y + w2*v3.z + w3*v3.w;
            }
            red[khalf*512 + 0*128 + r] = a0;
            red[khalf*512 + 1*128 + r] = a1;
            red[khalf*512 + 2*128 + r] = a2;
            red[khalf*512 + 3*128 + r] = a3;
        }
        __syncthreads();

        if (tid < 128) {
            const int b = tid >> 5;
            float s0 = bias_s[0*32 + aj] + xv0 + red[b*128 + 0*32 + aj] + red[512 + b*128 + 0*32 + aj];
            float s1 = bias_s[1*32 + aj] + xv1 + red[b*128 + 1*32 + aj] + red[512 + b*128 + 1*32 + aj];
            float s2 = bias_s[2*32 + aj] + xv2 + red[b*128 + 2*32 + aj] + red[512 + b*128 + 2*32 + aj];
            float s3 = bias_s[3*32 + aj] + xv3 + red[b*128 + 3*32 + aj] + red[512 + b*128 + 3*32 + aj];
            float i_ = sigf(s0), f_ = sigf(s1), gg = tanh_(s2), o_ = sigf(s3);
            float cc = f_*c_reg + i_*gg;
            c_reg = cc;
            float h = o_*tanh_(cc);
            g_hs[(abg*256 + tcur)*512 + dir*256 + au] = h;   // for proj
            // broadcast h into all 8 cluster CTAs' hsm[wb]
            const uint32_t laddr = hsm_a + (uint32_t)(wb*1024 + b*256 + au)*4u;
            #pragma unroll
            for (int rr = 0; rr < 8; ++rr) st_cluster_f32(laddr, rr, h);
        }
        CLUSTER_SYNC();   // orders DSMEM writes; all CTAs' hsm[wb] complete
    }
}

// ---- feats = hs @ projW^T + b ----
__global__ void proj_kernel(const float* __restrict__ projW,
                            const float* __restrict__ projb)
{
    extern __shared__ float sm[];
    float* pw = sm;               // [512][33]
    float* hr = pw + 512*33;      // [8][512]
    const int tid = threadIdx.x;
    for (int u = tid; u < 32*512; u += 256) {
        int l = u >> 9, k = u & 511;
        pw[k*33 + l] = projW[u];
    }
    int row0 = blockIdx.x*8;
    for (int u = tid; u < 1024; u += 256)
        ((float4*)hr)[u] = ((const float4*)&g_hs[row0*512])[u];
    __syncthreads();

    int r = tid >> 5, l = tid & 31;
    float acc = projb[l];
    #pragma unroll 4
    for (int k4 = 0; k4 < 128; ++k4) {
        float4 h4 = ((float4*)hr)[r*128 + k4];
        acc += h4.x*pw[(k4*4+0)*33 + l] + h4.y*pw[(k4*4+1)*33 + l]
             + h4.z*pw[(k4*4+2)*33 + l] + h4.w*pw[(k4*4+3)*33 + l];
    }
    g_feats[(row0 + r)*32 + l] = acc;
}

// ---- viterbi: one warp per batch element ----
__global__ void viterbi_kernel(const float* __restrict__ trans, float* __restrict__ out)
{
    __shared__ float fv[32];
    __shared__ float tr[32*33];
    __shared__ unsigned char bpv[256*32];
    const int l = threadIdx.x, b = blockIdx.x;
    for (int u = l; u < 1024; u += 32) tr[(u>>5)*33 + (u&31)] = trans[u];
    fv[l] = -10000.0f;
    __syncwarp();

    for (int t = 0; t < 256; ++t) {
        float m = -1e30f; int am = 0;
        #pragma unroll
        for (int pi = 0; pi < 32; ++pi) {
            float s = fv[pi] + tr[l*33 + pi];
            if (s > m) { m = s; am = pi; }
        }
        bpv[t*32 + l] = (unsigned char)am;
        float nf = m + g_feats[(b*256 + t)*32 + l];
        __syncwarp();
        fv[l] = nf;
        __syncwarp();
    }
    if (l == 0) {
        float bm = fv[0]; int bt = 0;
        for (int pi = 1; pi < 32; ++pi) if (fv[pi] > bm) { bm = fv[pi]; bt = pi; }
        out[b] = bm;
        int tag = bt;
        for (int t = 255; t >= 0; --t) {
            out[32 + b*256 + t] = (float)tag;
            tag = (int)bpv[t*32 + tag];
        }
    }
}

extern "C" void kernel_launch(void* const* d_in, const int* in_sizes, int n_in,
                              void* d_out, int out_size)
{
    const int* sent = (const int*)d_in[0];
    const int* cseq = (const int*)d_in[1];
    const float* const* F = (const float* const*)(d_in + 2);
    // F: 0 emb, 1 char_emb, 2..5 cWih_f,cWhh_f,cbih_f,cbhh_f, 6..9 backward,
    //    10..13 wWih_f,wWhh_f,wbih_f,wbhh_f, 14..17 backward, 18 proj_W, 19 proj_b, 20 trans
    float* out = (float*)d_out;

    cudaFuncSetAttribute(char_rec_kernel,  cudaFuncAttributeMaxDynamicSharedMemorySize, 100000);
    cudaFuncSetAttribute(proj_kernel,      cudaFuncAttributeMaxDynamicSharedMemorySize, 90000);

    ctab_kernel<<<dim3(CV_, 2), 256>>>(F[1], F[2], F[6]);
    char_rec_kernel<<<dim3(NROW/8, 2), 256, 79104>>>(
        F[3], F[4], F[5], F[7], F[8], F[9], cseq, sent, F[0]);
    wih_gemm_kernel<<<dim3(NROW/128, 1024/64, 2), 256>>>(F[10], F[14]);
    word_lstm_kernel<<<128, 256>>>(F[11], F[15], F[12], F[13], F[16], F[17]);
    proj_kernel<<<NROW/8, 256, 83968>>>(F[18], F[19]);
    viterbi_kernel<<<BB, 32>>>(F[20], out);
}

// round 12
// speedup vs baseline: 2.3408x; 1.0881x over previous
#include <cuda_runtime.h>
#include <cstdint>

#define BB 32
#define TT_ 256
#define CHL 16
#define CE_ 64
#define HC_ 64
#define HW_ 256
#define EMB_ 300
#define EIN_ 428
#define XS_ 432
#define LL_ 32
#define CV_ 128
#define NROW (BB*TT_)

__device__ float g_x[NROW*XS_];
__device__ float g_xg[2][NROW*1024];          // natural: [dir][m][gate]
__device__ float g_ctab[2][CV_*256];          // char input-projection table
__device__ float g_hs[NROW*512];              // [row][dir*256+k]  (for proj)
__device__ float g_feats[NROW*LL_];

__device__ __forceinline__ float sigf(float x) { return 1.0f/(1.0f+__expf(-x)); }
__device__ __forceinline__ float tanh_(float x) {
    x = fmaxf(x, -43.0f);
    float e = __expf(-2.0f*x);
    return (1.0f - e)/(1.0f + e);
}

__device__ __forceinline__ uint32_t smem_u32(const void* p) {
    uint32_t a;
    asm("{ .reg .u64 t; cvta.to.shared.u64 t, %1; cvt.u32.u64 %0, t; }"
        : "=r"(a) : "l"(p));
    return a;
}
#define CLUSTER_SYNC() do { \
    asm volatile("barrier.cluster.arrive.aligned;" ::: "memory"); \
    asm volatile("barrier.cluster.wait.aligned;" ::: "memory"); \
} while(0)

__device__ __forceinline__ void mbar_init(uint32_t addr, uint32_t cnt) {
    asm volatile("mbarrier.init.shared.b64 [%0], %1;" :: "r"(addr), "r"(cnt) : "memory");
}
__device__ __forceinline__ void mbar_expect_tx(uint32_t addr, uint32_t bytes) {
    asm volatile("mbarrier.arrive.expect_tx.shared.b64 _, [%0], %1;"
                 :: "r"(addr), "r"(bytes) : "memory");
}
__device__ __forceinline__ void mbar_wait(uint32_t addr, uint32_t parity) {
    asm volatile(
        "{\n\t.reg .pred P;\n\t"
        "W_%=:\n\t"
        "mbarrier.try_wait.parity.acquire.cta.shared::cta.b64 P, [%0], %1, 0x989680;\n\t"
        "@P bra D_%=;\n\t"
        "bra W_%=;\n\t"
        "D_%=:\n\t}"
        :: "r"(addr), "r"(parity) : "memory");
}

// ---- ctab[dir][c][g] = char_emb[c] . Wih[g]  (only 128 distinct chars) ----
__global__ void ctab_kernel(const float* __restrict__ char_emb,
                            const float* __restrict__ Wf,
                            const float* __restrict__ Wb)
{
    __shared__ float e[64];
    const int c = blockIdx.x, dir = blockIdx.y;
    const float* W = dir ? Wb : Wf;
    const int g = threadIdx.x;
    if (g < 64) e[g] = char_emb[c*64 + g];
    __syncthreads();
    float s = 0.f;
    #pragma unroll
    for (int k = 0; k < 64; ++k) s += e[k]*W[g*64 + k];
    g_ctab[dir][c*256 + g] = s;
}

// ---- char recurrence + x assembly: 8 seqs/block, dir = blockIdx.y ----
__global__ void char_rec_kernel(
    const float* __restrict__ Whh_f, const float* __restrict__ bih_f, const float* __restrict__ bhh_f,
    const float* __restrict__ Whh_b, const float* __restrict__ bih_b, const float* __restrict__ bhh_b,
    const int* __restrict__ cseq,
    const int* __restrict__ sentence, const float* __restrict__ emb)
{
    extern __shared__ float sm[];
    const int P = 257;
    float* WhhT = sm;                 // [64][257]
    float* bsum = WhhT + 64*P;        // [256]
    float* hsm  = bsum + 256;         // [8][64]
    float* csm  = hsm + 512;          // [8][64]
    float* gts  = csm + 512;          // [8][256]
    __shared__ int cid[128];

    const int dir = blockIdx.y;
    const float* Whh = dir ? Whh_b : Whh_f;
    const float* bih = dir ? bih_b : bih_f;
    const float* bhh = dir ? bhh_b : bhh_f;
    const float* tab = g_ctab[dir];
    const int tid = threadIdx.x;
    const int seq0 = blockIdx.x*8;

    for (int u = tid; u < 256*64; u += 256) {
        int g = u >> 6, k = u & 63;
        WhhT[k*P + g] = Whh[u];
    }
    bsum[tid] = bih[tid] + bhh[tid];
    if (tid < 128) cid[tid] = cseq[seq0*CHL + tid];
    for (int u = tid; u < 512; u += 256) { hsm[u] = 0.f; csm[u] = 0.f; }
    __syncthreads();

    const int g = tid;
    for (int step = 0; step < 16; ++step) {
        int tcur = dir ? (15 - step) : step;
        float acc[8];
        #pragma unroll
        for (int s = 0; s < 8; ++s)
            acc[s] = bsum[g] + tab[cid[s*16 + tcur]*256 + g];
        #pragma unroll 4
        for (int k4 = 0; k4 < 16; ++k4) {
            float w[4];
            #pragma unroll
            for (int j = 0; j < 4; ++j) w[j] = WhhT[(k4*4+j)*P + g];
            #pragma unroll
            for (int s = 0; s < 8; ++s) {
                float4 h = ((float4*)hsm)[s*16 + k4];
                acc[s] += w[0]*h.x + w[1]*h.y + w[2]*h.z + w[3]*h.w;
            }
        }
        #pragma unroll
        for (int s = 0; s < 8; ++s) gts[s*256 + g] = acc[s];
        __syncthreads();
        #pragma unroll
        for (int r = 0; r < 2; ++r) {
            int u = tid + r*256;
            int s = u >> 6, j = u & 63;
            float i_ = sigf(gts[s*256 + j]);
            float f_ = sigf(gts[s*256 + 64 + j]);
            float gg = tanh_(gts[s*256 + 128 + j]);
            float o_ = sigf(gts[s*256 + 192 + j]);
            float c = f_*csm[u] + i_*gg;
            csm[u] = c;
            hsm[u] = o_*tanh_(c);
        }
        __syncthreads();
    }

    const int off = 300 + (dir ? 0 : 64);
    #pragma unroll
    for (int r = 0; r < 2; ++r) {
        int u = tid + r*256;
        int s = u >> 6, j = u & 63;
        g_x[(seq0 + s)*XS_ + off + j] = hsm[u];
    }
    if (dir == 1) {
        for (int u = tid; u < 600; u += 256) {
            int s = u / 75, f4 = u % 75;
            int row = seq0 + s;
            int w = sentence[row];
            ((float4*)&g_x[row*XS_])[f4] = ((const float4*)&emb[w*EMB_])[f4];
        }
        if (tid < 8)
            *(float4*)&g_x[(seq0 + tid)*XS_ + 428] = make_float4(0.f,0.f,0.f,0.f);
    }
}

// ---- xg[dir] = x @ Wih^T (128x64 tile), coalesced natural epilogue ----
__global__ void wih_gemm_kernel(const float* __restrict__ Wf,
                                const float* __restrict__ Wb)
{
    __shared__ float As[16*132];
    __shared__ float Bs[16*68];
    const int dir = blockIdx.z;
    const float* W = dir ? Wb : Wf;
    float* Cout = g_xg[dir];
    const int m0 = blockIdx.x*128, n0 = blockIdx.y*64;
    const int tid = threadIdx.x;
    const int tm = tid >> 4, tn = tid & 15;
    const int ar = tid >> 1, ac = tid & 1;
    const int br = tid >> 2, bc = tid & 3;

    float acc[8][4];
    #pragma unroll
    for (int i = 0; i < 8; ++i)
        #pragma unroll
        for (int j = 0; j < 4; ++j) acc[i][j] = 0.f;

    for (int k0 = 0; k0 < XS_; k0 += 16) {
        const float4* arow = (const float4*)&g_x[(m0+ar)*XS_ + k0];
        float4 a0 = arow[ac*2];
        float4 a1 = arow[ac*2+1];
        int kk = k0 + bc*4;
        float4 bv = make_float4(0.f,0.f,0.f,0.f);
        if (kk + 4 <= EIN_) bv = *(const float4*)&W[(n0+br)*EIN_ + kk];
        As[(ac*8+0)*132+ar]=a0.x; As[(ac*8+1)*132+ar]=a0.y;
        As[(ac*8+2)*132+ar]=a0.z; As[(ac*8+3)*132+ar]=a0.w;
        As[(ac*8+4)*132+ar]=a1.x; As[(ac*8+5)*132+ar]=a1.y;
        As[(ac*8+6)*132+ar]=a1.z; As[(ac*8+7)*132+ar]=a1.w;
        Bs[(bc*4+0)*68+br]=bv.x; Bs[(bc*4+1)*68+br]=bv.y;
        Bs[(bc*4+2)*68+br]=bv.z; Bs[(bc*4+3)*68+br]=bv.w;
        __syncthreads();
        #pragma unroll
        for (int k = 0; k < 16; ++k) {
            float4 aA = ((float4*)&As[k*132])[tm*2];
            float4 aB = ((float4*)&As[k*132])[tm*2+1];
            float4 b4 = ((float4*)&Bs[k*68])[tn];
            float av[8] = {aA.x,aA.y,aA.z,aA.w,aB.x,aB.y,aB.z,aB.w};
            #pragma unroll
            for (int i = 0; i < 8; ++i) {
                acc[i][0] += av[i]*b4.x; acc[i][1] += av[i]*b4.y;
                acc[i][2] += av[i]*b4.z; acc[i][3] += av[i]*b4.w;
            }
        }
        __syncthreads();
    }
    #pragma unroll
    for (int i = 0; i < 8; ++i)
        *(float4*)&Cout[(m0 + tm*8 + i)*1024 + n0 + tn*4] =
            make_float4(acc[i][0], acc[i][1], acc[i][2], acc[i][3]);
}

// ---- word BiLSTM v5: clusters of 8, st.async + mbarrier ring exchange ----
// blockIdx.x: dir = bx>>6, group = (bx>>3)&7 (4 batches), rank c = bx&7 (32 units)
__global__ void __launch_bounds__(256, 1) __cluster_dims__(8, 1, 1)
word_lstm_kernel(
    const float* __restrict__ Whh_f, const float* __restrict__ Whh_b,
    const float* __restrict__ bih_f, const float* __restrict__ bhh_f,
    const float* __restrict__ bih_b, const float* __restrict__ bhh_b)
{
    // blob layout (bytes):
    // [0,16384)      ring: float[4][1024]    ([buf][b*256+k])
    // [16384,16400)  mbar[2] (u64)
    // [16400,20496)  red: float[2][4][128]   ([khalf][b][row])
    // [20496,21008)  bias: float[128]
    __shared__ __align__(16) unsigned char blob[21008];
    float* ring    = (float*)blob;
    float* red     = (float*)(blob + 16400);
    float* bias_s  = (float*)(blob + 20496);
    const uint32_t blob_a = smem_u32(blob);
    const uint32_t mbar_a = blob_a + 16384u;

    const int tid = threadIdx.x;
    const int dir = blockIdx.x >> 6;
    const int grp = (blockIdx.x >> 3) & 7;
    const int c   = blockIdx.x & 7;     // == cluster rank
    const int u0  = c*32;
    const float* Whh = dir ? Whh_b : Whh_f;
    const float* bi  = dir ? bih_b : bih_f;
    const float* bh  = dir ? bhh_b : bhh_f;
    const float* xg  = g_xg[dir];

    // remote blob base per rank (mapa hoisted)
    uint32_t rblob[8];
    #pragma unroll
    for (int rr = 0; rr < 8; ++rr)
        asm("mapa.shared::cluster.u32 %0, %1, %2;" : "=r"(rblob[rr]) : "r"(blob_a), "r"(rr));

    const int r = tid & 127, khalf = tid >> 7;
    const int q = r >> 5, j = r & 31;
    const int grow = q*256 + u0 + j;

    // weights into registers: 128 floats (this row's k-half)
    float w[128];
    #pragma unroll
    for (int i = 0; i < 32; ++i)
        ((float4*)w)[i] = *(const float4*)&Whh[grow*256 + khalf*128 + i*4];
    if (khalf == 0) bias_s[r] = bi[grow] + bh[grow];

    // activation-thread state (tid<128): owns (b = tid>>5, unit aj = tid&31)
    const int aj = tid & 31;
    const int au = u0 + aj;
    const int abg = grp*4 + (tid >> 5);             // global batch (tid<128)
    float c_reg = 0.f;

    ((float4*)(ring + 3*1024))[tid] = make_float4(0.f,0.f,0.f,0.f);  // buf3 = h0 = 0
    if (tid == 0) { mbar_init(mbar_a, 1u); mbar_init(mbar_a + 8u, 1u); }
    __syncthreads();
    CLUSTER_SYNC();   // peers' ring/mbar initialized before any st.async

    for (int it = 0; it < 256; ++it) {
        const int tcur = dir ? (255 - it) : it;
        const int rbuf = (it + 3) & 3, wbuf = it & 3;

        if (tid == 0)
            mbar_expect_tx(mbar_a + (uint32_t)(it & 1)*8u, 4096u);   // this step's incoming h

        // prefetch xg (hidden under wait + FMA loop)
        float xv0=0.f, xv1=0.f, xv2=0.f, xv3=0.f;
        if (tid < 128) {
            const float* xr = &xg[(abg*256 + tcur)*1024 + au];
            xv0 = xr[0]; xv1 = xr[256]; xv2 = xr[512]; xv3 = xr[768];
        }

        if (it > 0 && tid == 0)
            mbar_wait(mbar_a + (uint32_t)((it-1) & 1)*8u, (uint32_t)(((it-1) >> 1) & 1));
        __syncthreads();   // gates everyone on h-ready; also protects red reuse

        // gates: 4 batch accumulators, k-half dot with register weights
        {
            const float4* h0 = (const float4*)&ring[rbuf*1024 + 0*256 + khalf*128];
            const float4* h1 = (const float4*)&ring[rbuf*1024 + 1*256 + khalf*128];
            const float4* h2 = (const float4*)&ring[rbuf*1024 + 2*256 + khalf*128];
            const float4* h3 = (const float4*)&ring[rbuf*1024 + 3*256 + khalf*128];
            float a0=0.f, a1=0.f, a2=0.f, a3=0.f;
            #pragma unroll
            for (int k4 = 0; k4 < 32; ++k4) {
                float w0 = w[k4*4], w1 = w[k4*4+1], w2 = w[k4*4+2], w3 = w[k4*4+3];
                float4 v0 = h0[k4], v1 = h1[k4], v2 = h2[k4], v3 = h3[k4];
                a0 += w0*v0.x + w1*v0.y + w2*v0.z + w3*v0.w;
                a1 += w0*v1.x + w1*v1.y + w2*v1.z + w3*v1.w;
                a2 += w0*v2.x + w1*v2.y + w2*v2.z + w3*v2.w;
                a3 += w0*v3.x + w1*v3.y + w2*v3.z + w3*v3.w;
            }
            red[khalf*512 + 0*128 + r] = a0;
            red[khalf*512 + 1*128 + r] = a1;
            red[khalf*512 + 2*128 + r] = a2;
            red[khalf*512 + 3*128 + r] = a3;
        }
        __syncthreads();

        if (tid < 128) {
            const int b = tid >> 5;
            float s0 = bias_s[0*32 + aj] + xv0 + red[b*128 + 0*32 + aj] + red[512 + b*128 + 0*32 + aj];
            float s1 = bias_s[1*32 + aj] + xv1 + red[b*128 + 1*32 + aj] + red[512 + b*128 + 1*32 + aj];
            float s2 = bias_s[2*32 + aj] + xv2 + red[b*128 + 2*32 + aj] + red[512 + b*128 + 2*32 + aj];
            float s3 = bias_s[3*32 + aj] + xv3 + red[b*128 + 3*32 + aj] + red[512 + b*128 + 3*32 + aj];
            float i_ = sigf(s0), f_ = sigf(s1), gg = tanh_(s2), o_ = sigf(s3);
            float cc = f_*c_reg + i_*gg;
            c_reg = cc;
            float h = o_*tanh_(cc);
            g_hs[(abg*256 + tcur)*512 + dir*256 + au] = h;   // for proj
            // async-broadcast h into all 8 CTAs' ring[wbuf] with tx accounting
            const uint32_t off   = (uint32_t)(wbuf*1024 + b*256 + au)*4u;
            const uint32_t mboff = 16384u + (uint32_t)(it & 1)*8u;
            const uint32_t hv = __float_as_uint(h);
            #pragma unroll
            for (int rr = 0; rr < 8; ++rr) {
                asm volatile(
                    "st.async.shared::cluster.mbarrier::complete_tx::bytes.u32 [%0], %1, [%2];"
                    :: "r"(rblob[rr] + off), "r"(hv), "r"(rblob[rr] + mboff) : "memory");
            }
        }
        // next iteration's wait provides the step boundary
    }
    CLUSTER_SYNC();   // no CTA exits while peers' st.async may be in flight
}

// ---- feats = hs @ projW^T + b ----
__global__ void proj_kernel(const float* __restrict__ projW,
                            const float* __restrict__ projb)
{
    extern __shared__ float sm[];
    float* pw = sm;               // [512][33]
    float* hr = pw + 512*33;      // [8][512]
    const int tid = threadIdx.x;
    for (int u = tid; u < 32*512; u += 256) {
        int l = u >> 9, k = u & 511;
        pw[k*33 + l] = projW[u];
    }
    int row0 = blockIdx.x*8;
    for (int u = tid; u < 1024; u += 256)
        ((float4*)hr)[u] = ((const float4*)&g_hs[row0*512])[u];
    __syncthreads();

    int r = tid >> 5, l = tid & 31;
    float acc = projb[l];
    #pragma unroll 4
    for (int k4 = 0; k4 < 128; ++k4) {
        float4 h4 = ((float4*)hr)[r*128 + k4];
        acc += h4.x*pw[(k4*4+0)*33 + l] + h4.y*pw[(k4*4+1)*33 + l]
             + h4.z*pw[(k4*4+2)*33 + l] + h4.w*pw[(k4*4+3)*33 + l];
    }
    g_feats[(row0 + r)*32 + l] = acc;
}

// ---- viterbi: one warp per batch element ----
__global__ void viterbi_kernel(const float* __restrict__ trans, float* __restrict__ out)
{
    __shared__ float fv[32];
    __shared__ float tr[32*33];
    __shared__ unsigned char bpv[256*32];
    const int l = threadIdx.x, b = blockIdx.x;
    for (int u = l; u < 1024; u += 32) tr[(u>>5)*33 + (u&31)] = trans[u];
    fv[l] = -10000.0f;
    __syncwarp();

    for (int t = 0; t < 256; ++t) {
        float m = -1e30f; int am = 0;
        #pragma unroll
        for (int pi = 0; pi < 32; ++pi) {
            float s = fv[pi] + tr[l*33 + pi];
            if (s > m) { m = s; am = pi; }
        }
        bpv[t*32 + l] = (unsigned char)am;
        float nf = m + g_feats[(b*256 + t)*32 + l];
        __syncwarp();
        fv[l] = nf;
        __syncwarp();
    }
    if (l == 0) {
        float bm = fv[0]; int bt = 0;
        for (int pi = 1; pi < 32; ++pi) if (fv[pi] > bm) { bm = fv[pi]; bt = pi; }
        out[b] = bm;
        int tag = bt;
        for (int t = 255; t >= 0; --t) {
            out[32 + b*256 + t] = (float)tag;
            tag = (int)bpv[t*32 + tag];
        }
    }
}

extern "C" void kernel_launch(void* const* d_in, const int* in_sizes, int n_in,
                              void* d_out, int out_size)
{
    const int* sent = (const int*)d_in[0];
    const int* cseq = (const int*)d_in[1];
    const float* const* F = (const float* const*)(d_in + 2);
    // F: 0 emb, 1 char_emb, 2..5 cWih_f,cWhh_f,cbih_f,cbhh_f, 6..9 backward,
    //    10..13 wWih_f,wWhh_f,wbih_f,wbhh_f, 14..17 backward, 18 proj_W, 19 proj_b, 20 trans
    float* out = (float*)d_out;

    cudaFuncSetAttribute(char_rec_kernel,  cudaFuncAttributeMaxDynamicSharedMemorySize, 100000);
    cudaFuncSetAttribute(proj_kernel,      cudaFuncAttributeMaxDynamicSharedMemorySize, 90000);

    ctab_kernel<<<dim3(CV_, 2), 256>>>(F[1], F[2], F[6]);
    char_rec_kernel<<<dim3(NROW/8, 2), 256, 79104>>>(
        F[3], F[4], F[5], F[7], F[8], F[9], cseq, sent, F[0]);
    wih_gemm_kernel<<<dim3(NROW/128, 1024/64, 2), 256>>>(F[10], F[14]);
    word_lstm_kernel<<<128, 256>>>(F[11], F[15], F[12], F[13], F[16], F[17]);
    proj_kernel<<<NROW/8, 256, 83968>>>(F[18], F[19]);
    viterbi_kernel<<<BB, 32>>>(F[20], out);
}

// round 13
// speedup vs baseline: 2.4459x; 1.0449x over previous
#include <cuda_runtime.h>
#include <cstdint>

#define BB 32
#define TT_ 256
#define CHL 16
#define CE_ 64
#define HC_ 64
#define HW_ 256
#define EMB_ 300
#define EIN_ 428
#define XS_ 432
#define LL_ 32
#define CV_ 128
#define NROW (BB*TT_)

typedef unsigned long long ull;

__device__ float g_x[NROW*XS_];
__device__ float g_xg[2][NROW*1024];          // natural: [dir][m][gate]
__device__ float g_ctab[2][CV_*256];          // char input-projection table
__device__ float g_hs[NROW*512];              // [row][dir*256+k]  (for proj)
__device__ float g_feats[NROW*LL_];

__device__ __forceinline__ float sigf(float x) { return 1.0f/(1.0f+__expf(-x)); }
__device__ __forceinline__ float tanh_(float x) {
    x = fmaxf(x, -43.0f);
    float e = __expf(-2.0f*x);
    return (1.0f - e)/(1.0f + e);
}

// ---- packed f32x2 helpers (sm_100+) ----
__device__ __forceinline__ ull fma2(ull a, ull b, ull c) {
    ull d;
    asm("fma.rn.f32x2 %0, %1, %2, %3;" : "=l"(d) : "l"(a), "l"(b), "l"(c));
    return d;
}
__device__ __forceinline__ ull dup2(float x) {
    ull d;
    asm("mov.b64 %0, {%1, %1};" : "=l"(d) : "f"(x));
    return d;
}
__device__ __forceinline__ float2 unpack2(ull v) {
    float2 r;
    asm("mov.b64 {%0, %1}, %2;" : "=f"(r.x), "=f"(r.y) : "l"(v));
    return r;
}
__device__ __forceinline__ float hsum2(ull v) {
    float2 r = unpack2(v);
    return r.x + r.y;
}
__device__ __forceinline__ ull pack2(float lo, float hi) {
    ull d;
    asm("mov.b64 %0, {%1, %2};" : "=l"(d) : "f"(lo), "f"(hi));
    return d;
}

__device__ __forceinline__ uint32_t smem_u32(const void* p) {
    uint32_t a;
    asm("{ .reg .u64 t; cvta.to.shared.u64 t, %1; cvt.u32.u64 %0, t; }"
        : "=r"(a) : "l"(p));
    return a;
}
#define CLUSTER_SYNC() do { \
    asm volatile("barrier.cluster.arrive.aligned;" ::: "memory"); \
    asm volatile("barrier.cluster.wait.aligned;" ::: "memory"); \
} while(0)

__device__ __forceinline__ void mbar_init(uint32_t addr, uint32_t cnt) {
    asm volatile("mbarrier.init.shared.b64 [%0], %1;" :: "r"(addr), "r"(cnt) : "memory");
}
__device__ __forceinline__ void mbar_expect_tx(uint32_t addr, uint32_t bytes) {
    asm volatile("mbarrier.arrive.expect_tx.shared.b64 _, [%0], %1;"
                 :: "r"(addr), "r"(bytes) : "memory");
}
__device__ __forceinline__ void mbar_wait(uint32_t addr, uint32_t parity) {
    asm volatile(
        "{\n\t.reg .pred P;\n\t"
        "W_%=:\n\t"
        "mbarrier.try_wait.parity.acquire.cta.shared::cta.b64 P, [%0], %1, 0x989680;\n\t"
        "@P bra D_%=;\n\t"
        "bra W_%=;\n\t"
        "D_%=:\n\t}"
        :: "r"(addr), "r"(parity) : "memory");
}

// ---- ctab[dir][c][g] = char_emb[c] . Wih[g]  (only 128 distinct chars) ----
__global__ void ctab_kernel(const float* __restrict__ char_emb,
                            const float* __restrict__ Wf,
                            const float* __restrict__ Wb)
{
    __shared__ float e[64];
    const int c = blockIdx.x, dir = blockIdx.y;
    const float* W = dir ? Wb : Wf;
    const int g = threadIdx.x;
    if (g < 64) e[g] = char_emb[c*64 + g];
    __syncthreads();
    float s = 0.f;
    #pragma unroll
    for (int k = 0; k < 64; ++k) s += e[k]*W[g*64 + k];
    g_ctab[dir][c*256 + g] = s;
}

// ---- char recurrence + x assembly: 8 seqs/block, dir = blockIdx.y, f32x2 ----
__global__ void char_rec_kernel(
    const float* __restrict__ Whh_f, const float* __restrict__ bih_f, const float* __restrict__ bhh_f,
    const float* __restrict__ Whh_b, const float* __restrict__ bih_b, const float* __restrict__ bhh_b,
    const int* __restrict__ cseq,
    const int* __restrict__ sentence, const float* __restrict__ emb)
{
    extern __shared__ __align__(16) unsigned char smraw[];
    const int P = 257;
    ull*   WhhP = (ull*)smraw;                 // [32 k2][257] packed (W[g][2k2],W[g][2k2+1])
    float* bsum = (float*)(WhhP + 32*P);       // [256]
    float* hsm  = bsum + 256;                  // [8][64]
    float* csm  = hsm + 512;                   // [8][64]
    float* gts  = csm + 512;                   // [8][256]
    __shared__ int cid[128];

    const int dir = blockIdx.y;
    const float* Whh = dir ? Whh_b : Whh_f;
    const float* bih = dir ? bih_b : bih_f;
    const float* bhh = dir ? bhh_b : bhh_f;
    const float* tab = g_ctab[dir];
    const int tid = threadIdx.x;
    const int seq0 = blockIdx.x*8;

    // Whh rows are 64 floats = 32 ulls, 8B-aligned; coalesced gmem ull reads
    const ull* Wp = (const ull*)Whh;           // [256][32]
    for (int u = tid; u < 256*32; u += 256) {
        int g = u >> 5, k2 = u & 31;
        WhhP[k2*P + g] = Wp[u];
    }
    bsum[tid] = bih[tid] + bhh[tid];
    if (tid < 128) cid[tid] = cseq[seq0*CHL + tid];
    for (int u = tid; u < 512; u += 256) { hsm[u] = 0.f; csm[u] = 0.f; }
    __syncthreads();

    const int g = tid;
    for (int step = 0; step < 16; ++step) {
        int tcur = dir ? (15 - step) : step;
        ull acc[8];
        #pragma unroll
        for (int s = 0; s < 8; ++s)
            acc[s] = pack2(bsum[g] + tab[cid[s*16 + tcur]*256 + g], 0.f);
        #pragma unroll 4
        for (int k4 = 0; k4 < 16; ++k4) {
            ull wa = WhhP[(2*k4)*P + g];
            ull wb = WhhP[(2*k4+1)*P + g];
            #pragma unroll
            for (int s = 0; s < 8; ++s) {
                ulonglong2 h2 = ((ulonglong2*)hsm)[s*16 + k4];
                acc[s] = fma2(wa, h2.x, acc[s]);
                acc[s] = fma2(wb, h2.y, acc[s]);
            }
        }
        #pragma unroll
        for (int s = 0; s < 8; ++s) gts[s*256 + g] = hsum2(acc[s]);
        __syncthreads();
        #pragma unroll
        for (int r = 0; r < 2; ++r) {
            int u = tid + r*256;
            int s = u >> 6, j = u & 63;
            float i_ = sigf(gts[s*256 + j]);
            float f_ = sigf(gts[s*256 + 64 + j]);
            float gg = tanh_(gts[s*256 + 128 + j]);
            float o_ = sigf(gts[s*256 + 192 + j]);
            float c = f_*csm[u] + i_*gg;
            csm[u] = c;
            hsm[u] = o_*tanh_(c);
        }
        __syncthreads();
    }

    const int off = 300 + (dir ? 0 : 64);
    #pragma unroll
    for (int r = 0; r < 2; ++r) {
        int u = tid + r*256;
        int s = u >> 6, j = u & 63;
        g_x[(seq0 + s)*XS_ + off + j] = hsm[u];
    }
    if (dir == 1) {
        for (int u = tid; u < 600; u += 256) {
            int s = u / 75, f4 = u % 75;
            int row = seq0 + s;
            int w = sentence[row];
            ((float4*)&g_x[row*XS_])[f4] = ((const float4*)&emb[w*EMB_])[f4];
        }
        if (tid < 8)
            *(float4*)&g_x[(seq0 + tid)*XS_ + 428] = make_float4(0.f,0.f,0.f,0.f);
    }
}

// ---- xg[dir] = x @ Wih^T (128x64 tile), f32x2 over row-pairs (bit-exact) ----
__global__ void wih_gemm_kernel(const float* __restrict__ Wf,
                                const float* __restrict__ Wb)
{
    __shared__ __align__(16) float As[16*132];
    __shared__ __align__(16) float Bs[16*68];
    const int dir = blockIdx.z;
    const float* W = dir ? Wb : Wf;
    float* Cout = g_xg[dir];
    const int m0 = blockIdx.x*128, n0 = blockIdx.y*64;
    const int tid = threadIdx.x;
    const int tm = tid >> 4, tn = tid & 15;
    const int ar = tid >> 1, ac = tid & 1;
    const int br = tid >> 2, bc = tid & 3;

    ull acc2[4][4];   // [row-pair i2][j] = (acc[2i2][j], acc[2i2+1][j])
    #pragma unroll
    for (int i = 0; i < 4; ++i)
        #pragma unroll
        for (int j = 0; j < 4; ++j) acc2[i][j] = 0ull;

    for (int k0 = 0; k0 < XS_; k0 += 16) {
        const float4* arow = (const float4*)&g_x[(m0+ar)*XS_ + k0];
        float4 a0 = arow[ac*2];
        float4 a1 = arow[ac*2+1];
        int kk = k0 + bc*4;
        float4 bv = make_float4(0.f,0.f,0.f,0.f);
        if (kk + 4 <= EIN_) bv = *(const float4*)&W[(n0+br)*EIN_ + kk];
        As[(ac*8+0)*132+ar]=a0.x; As[(ac*8+1)*132+ar]=a0.y;
        As[(ac*8+2)*132+ar]=a0.z; As[(ac*8+3)*132+ar]=a0.w;
        As[(ac*8+4)*132+ar]=a1.x; As[(ac*8+5)*132+ar]=a1.y;
        As[(ac*8+6)*132+ar]=a1.z; As[(ac*8+7)*132+ar]=a1.w;
        Bs[(bc*4+0)*68+br]=bv.x; Bs[(bc*4+1)*68+br]=bv.y;
        Bs[(bc*4+2)*68+br]=bv.z; Bs[(bc*4+3)*68+br]=bv.w;
        __syncthreads();
        #pragma unroll
        for (int k = 0; k < 16; ++k) {
            // (av0,av1),(av2,av3),(av4,av5),(av6,av7) packed pairs
            ulonglong2 aA = ((const ulonglong2*)&As[k*132])[tm*2];
            ulonglong2 aB = ((const ulonglong2*)&As[k*132])[tm*2+1];
            float4 b4 = ((float4*)&Bs[k*68])[tn];
            ull bd0 = dup2(b4.x), bd1 = dup2(b4.y), bd2 = dup2(b4.z), bd3 = dup2(b4.w);
            acc2[0][0]=fma2(aA.x,bd0,acc2[0][0]); acc2[0][1]=fma2(aA.x,bd1,acc2[0][1]);
            acc2[0][2]=fma2(aA.x,bd2,acc2[0][2]); acc2[0][3]=fma2(aA.x,bd3,acc2[0][3]);
            acc2[1][0]=fma2(aA.y,bd0,acc2[1][0]); acc2[1][1]=fma2(aA.y,bd1,acc2[1][1]);
            acc2[1][2]=fma2(aA.y,bd2,acc2[1][2]); acc2[1][3]=fma2(aA.y,bd3,acc2[1][3]);
            acc2[2][0]=fma2(aB.x,bd0,acc2[2][0]); acc2[2][1]=fma2(aB.x,bd1,acc2[2][1]);
            acc2[2][2]=fma2(aB.x,bd2,acc2[2][2]); acc2[2][3]=fma2(aB.x,bd3,acc2[2][3]);
            acc2[3][0]=fma2(aB.y,bd0,acc2[3][0]); acc2[3][1]=fma2(aB.y,bd1,acc2[3][1]);
            acc2[3][2]=fma2(aB.y,bd2,acc2[3][2]); acc2[3][3]=fma2(aB.y,bd3,acc2[3][3]);
        }
        __syncthreads();
    }
    #pragma unroll
    for (int i2 = 0; i2 < 4; ++i2) {
        float2 p0 = unpack2(acc2[i2][0]);
        float2 p1 = unpack2(acc2[i2][1]);
        float2 p2 = unpack2(acc2[i2][2]);
        float2 p3 = unpack2(acc2[i2][3]);
        *(float4*)&Cout[(m0 + tm*8 + 2*i2    )*1024 + n0 + tn*4] =
            make_float4(p0.x, p1.x, p2.x, p3.x);
        *(float4*)&Cout[(m0 + tm*8 + 2*i2 + 1)*1024 + n0 + tn*4] =
            make_float4(p0.y, p1.y, p2.y, p3.y);
    }
}

// ---- word BiLSTM v6: clusters of 8, st.async mbarrier ring, f32x2 FMA ----
__global__ void __launch_bounds__(256, 1) __cluster_dims__(8, 1, 1)
word_lstm_kernel(
    const float* __restrict__ Whh_f, const float* __restrict__ Whh_b,
    const float* __restrict__ bih_f, const float* __restrict__ bhh_f,
    const float* __restrict__ bih_b, const float* __restrict__ bhh_b)
{
    // blob layout (bytes):
    // [0,16384)      ring: float[4][1024]
    // [16384,16400)  mbar[2]
    // [16400,20496)  red: float[2][4][128]
    // [20496,21008)  bias: float[128]
    __shared__ __align__(16) unsigned char blob[21008];
    float* ring    = (float*)blob;
    float* red     = (float*)(blob + 16400);
    float* bias_s  = (float*)(blob + 20496);
    const uint32_t blob_a = smem_u32(blob);
    const uint32_t mbar_a = blob_a + 16384u;

    const int tid = threadIdx.x;
    const int dir = blockIdx.x >> 6;
    const int grp = (blockIdx.x >> 3) & 7;
    const int c   = blockIdx.x & 7;     // == cluster rank
    const int u0  = c*32;
    const float* Whh = dir ? Whh_b : Whh_f;
    const float* bi  = dir ? bih_b : bih_f;
    const float* bh  = dir ? bhh_b : bhh_f;
    const float* xg  = g_xg[dir];

    uint32_t rblob[8];
    #pragma unroll
    for (int rr = 0; rr < 8; ++rr)
        asm("mapa.shared::cluster.u32 %0, %1, %2;" : "=r"(rblob[rr]) : "r"(blob_a), "r"(rr));

    const int r = tid & 127, khalf = tid >> 7;
    const int q = r >> 5, j = r & 31;
    const int grow = q*256 + u0 + j;

    // weights as packed k-pairs: 64 ulls = 128 floats (this row's k-half)
    ull w2[64];
    #pragma unroll
    for (int i = 0; i < 32; ++i)
        ((ulonglong2*)w2)[i] = ((const ulonglong2*)&Whh[grow*256 + khalf*128])[i];
    if (khalf == 0) bias_s[r] = bi[grow] + bh[grow];

    const int aj = tid & 31;
    const int au = u0 + aj;
    const int abg = grp*4 + (tid >> 5);             // global batch (tid<128)
    float c_reg = 0.f;

    ((float4*)(ring + 3*1024))[tid] = make_float4(0.f,0.f,0.f,0.f);  // buf3 = h0 = 0
    if (tid == 0) { mbar_init(mbar_a, 1u); mbar_init(mbar_a + 8u, 1u); }
    __syncthreads();
    CLUSTER_SYNC();

    for (int it = 0; it < 256; ++it) {
        const int tcur = dir ? (255 - it) : it;
        const int rbuf = (it + 3) & 3, wbuf = it & 3;

        if (tid == 0)
            mbar_expect_tx(mbar_a + (uint32_t)(it & 1)*8u, 4096u);

        float xv0=0.f, xv1=0.f, xv2=0.f, xv3=0.f;
        if (tid < 128) {
            const float* xr = &xg[(abg*256 + tcur)*1024 + au];
            xv0 = xr[0]; xv1 = xr[256]; xv2 = xr[512]; xv3 = xr[768];
        }

        if (it > 0 && tid == 0)
            mbar_wait(mbar_a + (uint32_t)((it-1) & 1)*8u, (uint32_t)(((it-1) >> 1) & 1));
        __syncthreads();

        // gates: 4 batch chains, f32x2 over even/odd k
        {
            const ulonglong2* h0 = (const ulonglong2*)&ring[rbuf*1024 + 0*256 + khalf*128];
            const ulonglong2* h1 = (const ulonglong2*)&ring[rbuf*1024 + 1*256 + khalf*128];
            const ulonglong2* h2 = (const ulonglong2*)&ring[rbuf*1024 + 2*256 + khalf*128];
            const ulonglong2* h3 = (const ulonglong2*)&ring[rbuf*1024 + 3*256 + khalf*128];
            ull A0=0ull, A1=0ull, A2=0ull, A3=0ull;
            #pragma unroll
            for (int k4 = 0; k4 < 32; ++k4) {
                ull wa = w2[k4*2], wb = w2[k4*2+1];
                ulonglong2 v0 = h0[k4], v1 = h1[k4], v2 = h2[k4], v3 = h3[k4];
                A0 = fma2(wa, v0.x, A0); A0 = fma2(wb, v0.y, A0);
                A1 = fma2(wa, v1.x, A1); A1 = fma2(wb, v1.y, A1);
                A2 = fma2(wa, v2.x, A2); A2 = fma2(wb, v2.y, A2);
                A3 = fma2(wa, v3.x, A3); A3 = fma2(wb, v3.y, A3);
            }
            red[khalf*512 + 0*128 + r] = hsum2(A0);
            red[khalf*512 + 1*128 + r] = hsum2(A1);
            red[khalf*512 + 2*128 + r] = hsum2(A2);
            red[khalf*512 + 3*128 + r] = hsum2(A3);
        }
        __syncthreads();

        if (tid < 128) {
            const int b = tid >> 5;
            float s0 = bias_s[0*32 + aj] + xv0 + red[b*128 + 0*32 + aj] + red[512 + b*128 + 0*32 + aj];
            float s1 = bias_s[1*32 + aj] + xv1 + red[b*128 + 1*32 + aj] + red[512 + b*128 + 1*32 + aj];
            float s2 = bias_s[2*32 + aj] + xv2 + red[b*128 + 2*32 + aj] + red[512 + b*128 + 2*32 + aj];
            float s3 = bias_s[3*32 + aj] + xv3 + red[b*128 + 3*32 + aj] + red[512 + b*128 + 3*32 + aj];
            float i_ = sigf(s0), f_ = sigf(s1), gg = tanh_(s2), o_ = sigf(s3);
            float cc = f_*c_reg + i_*gg;
            c_reg = cc;
            float h = o_*tanh_(cc);
            g_hs[(abg*256 + tcur)*512 + dir*256 + au] = h;   // for proj
            const uint32_t off   = (uint32_t)(wbuf*1024 + b*256 + au)*4u;
            const uint32_t mboff = 16384u + (uint32_t)(it & 1)*8u;
            const uint32_t hv = __float_as_uint(h);
            #pragma unroll
            for (int rr = 0; rr < 8; ++rr) {
                asm volatile(
                    "st.async.shared::cluster.mbarrier::complete_tx::bytes.u32 [%0], %1, [%2];"
                    :: "r"(rblob[rr] + off), "r"(hv), "r"(rblob[rr] + mboff) : "memory");
            }
        }
    }
    CLUSTER_SYNC();
}

// ---- feats = hs @ projW^T + b ----
__global__ void proj_kernel(const float* __restrict__ projW,
                            const float* __restrict__ projb)
{
    extern __shared__ float sm[];
    float* pw = sm;               // [512][33]
    float* hr = pw + 512*33;      // [8][512]
    const int tid = threadIdx.x;
    for (int u = tid; u < 32*512; u += 256) {
        int l = u >> 9, k = u & 511;
        pw[k*33 + l] = projW[u];
    }
    int row0 = blockIdx.x*8;
    for (int u = tid; u < 1024; u += 256)
        ((float4*)hr)[u] = ((const float4*)&g_hs[row0*512])[u];
    __syncthreads();

    int r = tid >> 5, l = tid & 31;
    float acc = projb[l];
    #pragma unroll 4
    for (int k4 = 0; k4 < 128; ++k4) {
        float4 h4 = ((float4*)hr)[r*128 + k4];
        acc += h4.x*pw[(k4*4+0)*33 + l] + h4.y*pw[(k4*4+1)*33 + l]
             + h4.z*pw[(k4*4+2)*33 + l] + h4.w*pw[(k4*4+3)*33 + l];
    }
    g_feats[(row0 + r)*32 + l] = acc;
}

// ---- viterbi: one warp per batch element ----
__global__ void viterbi_kernel(const float* __restrict__ trans, float* __restrict__ out)
{
    __shared__ float fv[32];
    __shared__ float tr[32*33];
    __shared__ unsigned char bpv[256*32];
    const int l = threadIdx.x, b = blockIdx.x;
    for (int u = l; u < 1024; u += 32) tr[(u>>5)*33 + (u&31)] = trans[u];
    fv[l] = -10000.0f;
    __syncwarp();

    for (int t = 0; t < 256; ++t) {
        float m = -1e30f; int am = 0;
        #pragma unroll
        for (int pi = 0; pi < 32; ++pi) {
            float s = fv[pi] + tr[l*33 + pi];
            if (s > m) { m = s; am = pi; }
        }
        bpv[t*32 + l] = (unsigned char)am;
        float nf = m + g_feats[(b*256 + t)*32 + l];
        __syncwarp();
        fv[l] = nf;
        __syncwarp();
    }
    if (l == 0) {
        float bm = fv[0]; int bt = 0;
        for (int pi = 1; pi < 32; ++pi) if (fv[pi] > bm) { bm = fv[pi]; bt = pi; }
        out[b] = bm;
        int tag = bt;
        for (int t = 255; t >= 0; --t) {
            out[32 + b*256 + t] = (float)tag;
            tag = (int)bpv[t*32 + tag];
        }
    }
}

extern "C" void kernel_launch(void* const* d_in, const int* in_sizes, int n_in,
                              void* d_out, int out_size)
{
    const int* sent = (const int*)d_in[0];
    const int* cseq = (const int*)d_in[1];
    const float* const* F = (const float* const*)(d_in + 2);
    // F: 0 emb, 1 char_emb, 2..5 cWih_f,cWhh_f,cbih_f,cbhh_f, 6..9 backward,
    //    10..13 wWih_f,wWhh_f,wbih_f,wbhh_f, 14..17 backward, 18 proj_W, 19 proj_b, 20 trans
    float* out = (float*)d_out;

    // char_rec smem: 32*257 ull (65792 B) + (256+512+512+2048)*4 = 13312 B -> 79104 B
    cudaFuncSetAttribute(char_rec_kernel,  cudaFuncAttributeMaxDynamicSharedMemorySize, 100000);
    cudaFuncSetAttribute(proj_kernel,      cudaFuncAttributeMaxDynamicSharedMemorySize, 90000);

    ctab_kernel<<<dim3(CV_, 2), 256>>>(F[1], F[2], F[6]);
    char_rec_kernel<<<dim3(NROW/8, 2), 256, 79104>>>(
        F[3], F[4], F[5], F[7], F[8], F[9], cseq, sent, F[0]);
    wih_gemm_kernel<<<dim3(NROW/128, 1024/64, 2), 256>>>(F[10], F[14]);
    word_lstm_kernel<<<128, 256>>>(F[11], F[15], F[12], F[13], F[16], F[17]);
    proj_kernel<<<NROW/8, 256, 83968>>>(F[18], F[19]);
    viterbi_kernel<<<BB, 32>>>(F[20], out);
}